// round 5
// baseline (speedup 1.0000x reference)
#include <cuda_runtime.h>

#define NN 16384
#define EE 131072
#define GG 32
#define BN_EPS 1e-5f

// ---------------- scratch (device globals; no allocation APIs) ----------------
__device__ float g_bufA[NN * 64];          // h1lin / sage-agg
__device__ float g_bufB[NN * 512];         // pre-BN conv outputs (gcn1, gcn4)
__device__ float g_bufC[NN * 256];         // sage lin (128) / gat out (256)
__device__ float g_h1[NN * 64];
__device__ float g_h2[NN * 128];
__device__ float g_h3[NN * 256];
__device__ float g_h4[NN * 512];
__device__ float g_h4lin[NN * 512];
__device__ float g_hgat[(long long)NN * 1024];
__device__ float g_es[NN * 4];
__device__ float g_ed[NN * 4];
__device__ float g_dis[NN];
__device__ int   g_indeg[NN];
__device__ int   g_rowptr[NN + 1];
__device__ int   g_cursor[NN];
__device__ int   g_csr[EE];
__device__ int   g_gcnt[GG];
__device__ int   g_goff[GG + 1];
__device__ float g_sum[512];
__device__ float g_sumsq[512];
__device__ float g_pooled[GG * 1024];
__device__ float* g_bp[9];                 // buffer pointer table (avoid symbol-address API)

__device__ __forceinline__ float lrelu(float x) { return x > 0.f ? x : 0.2f * x; }

// ---------------- setup: counts, pointer table ----------------
__global__ void init_kernel() {
    int idx = blockIdx.x * blockDim.x + threadIdx.x;
    if (idx == 0) {
        g_bp[0] = g_bufA; g_bp[1] = g_bufB; g_bp[2] = g_bufC;
        g_bp[3] = g_h1;   g_bp[4] = g_h2;   g_bp[5] = g_h3;
        g_bp[6] = g_h4;   g_bp[7] = g_h4lin; g_bp[8] = g_hgat;
    }
    if (idx < NN) g_indeg[idx] = 0;
    if (idx < GG) g_gcnt[idx] = 0;
}

__global__ void count_kernel(const int* __restrict__ dst, const int* __restrict__ batch) {
    int idx = blockIdx.x * blockDim.x + threadIdx.x;
    if (idx < EE) atomicAdd(&g_indeg[dst[idx]], 1);
    if (idx < NN) atomicAdd(&g_gcnt[batch[idx]], 1);
}

// single-block exclusive scan of indeg -> rowptr/cursor; also dis and graph offsets
__global__ void scan_kernel() {
    __shared__ int partial[1024];
    int t = threadIdx.x;                 // blockDim = 1024, 16 elems/thread
    int base = t * 16;
    int local[16];
    int s = 0;
    #pragma unroll
    for (int j = 0; j < 16; j++) { local[j] = s; s += g_indeg[base + j]; }
    partial[t] = s;
    __syncthreads();
    for (int off = 1; off < 1024; off <<= 1) {
        int v = (t >= off) ? partial[t - off] : 0;
        __syncthreads();
        partial[t] += v;
        __syncthreads();
    }
    int pre = (t == 0) ? 0 : partial[t - 1];
    #pragma unroll
    for (int j = 0; j < 16; j++) {
        int v = pre + local[j];
        g_rowptr[base + j] = v;
        g_cursor[base + j] = v;
        g_dis[base + j] = rsqrtf((float)(g_indeg[base + j] + 1));
    }
    if (t == 1023) g_rowptr[NN] = partial[1023];
    if (t == 0) {
        int a = 0;
        for (int g = 0; g < GG; g++) { g_goff[g] = a; a += g_gcnt[g]; }
        g_goff[GG] = a;
    }
}

__global__ void fill_csr_kernel(const int* __restrict__ src, const int* __restrict__ dst) {
    int idx = blockIdx.x * blockDim.x + threadIdx.x;
    if (idx < EE) {
        int pos = atomicAdd(&g_cursor[dst[idx]], 1);
        g_csr[pos] = src[idx];
    }
}

// ---------------- GCN1 linear (K=5 -> 64) ----------------
__global__ void lin1_kernel(const float* __restrict__ x, const float* __restrict__ w) {
    int i = blockIdx.x, c = threadIdx.x;   // blockDim = 64
    float acc = 0.f;
    #pragma unroll
    for (int k = 0; k < 5; k++) acc += x[i * 5 + k] * w[k * 64 + c];
    g_bufA[i * 64 + c] = acc;
}

// ---------------- GCN aggregate (width = blockDim.x) ----------------
__global__ void gcn_agg_kernel(int insel, int outsel, const float* __restrict__ bias) {
    const float* __restrict__ h = g_bp[insel];
    float* __restrict__ out = g_bp[outsel];
    int W = blockDim.x;
    int i = blockIdx.x, c = threadIdx.x;
    float di = g_dis[i];
    float acc = h[(size_t)i * W + c] * di * di;
    int e0 = g_rowptr[i], e1 = g_rowptr[i + 1];
    for (int e = e0; e < e1; e++) {
        int s = g_csr[e];
        acc += h[(size_t)s * W + c] * (g_dis[s] * di);
    }
    out[(size_t)i * W + c] = acc + bias[c];
}

// ---------------- SAGE mean aggregate (64-wide, h1 -> bufA) ----------------
__global__ void sage_agg_kernel() {
    int i = blockIdx.x, c = threadIdx.x;   // blockDim = 64
    int e0 = g_rowptr[i], e1 = g_rowptr[i + 1];
    float acc = 0.f;
    for (int e = e0; e < e1; e++) acc += g_h1[(size_t)g_csr[e] * 64 + c];
    int cnt = e1 - e0;
    g_bufA[i * 64 + c] = acc / (float)(cnt > 0 ? cnt : 1);
}

// ---------------- BN stats / apply (width = blockDim.x) ----------------
__global__ void zero_sums_kernel() { g_sum[threadIdx.x] = 0.f; g_sumsq[threadIdx.x] = 0.f; }

__global__ void bn_stats_kernel(int insel) {
    const float* __restrict__ h = g_bp[insel];
    int W = blockDim.x, c = threadIdx.x;
    float s = 0.f, s2 = 0.f;
    for (int r = blockIdx.x; r < NN; r += gridDim.x) {
        float v = h[(size_t)r * W + c];
        s += v; s2 += v * v;
    }
    atomicAdd(&g_sum[c], s);
    atomicAdd(&g_sumsq[c], s2);
}

__global__ void bn_apply_kernel(int insel, int outsel,
                                const float* __restrict__ gam, const float* __restrict__ bet) {
    const float* __restrict__ h = g_bp[insel];
    float* __restrict__ out = g_bp[outsel];
    int W = blockDim.x, c = threadIdx.x;
    float mean = g_sum[c] * (1.f / NN);
    float var = g_sumsq[c] * (1.f / NN) - mean * mean;
    float sc = gam[c] * rsqrtf(var + BN_EPS);
    float sh = bet[c] - mean * sc;
    for (int r = blockIdx.x; r < NN; r += gridDim.x) {
        float v = h[(size_t)r * W + c] * sc + sh;
        out[(size_t)r * W + c] = fmaxf(v, 0.f);
    }
}

// ---------------- SGEMM: C[NN,M] = A[NN,K] @ B[K,M] (f32x2 packed FMA) ----------------
__global__ __launch_bounds__(256)
void sgemm_kernel(int asel, const float* __restrict__ B, int csel,
                  const float* __restrict__ bias, int K, int M, int accumulate) {
    const float* __restrict__ A = g_bp[asel];
    float* __restrict__ C = g_bp[csel];
    __shared__ unsigned long long As2[8][128];   // A values pre-duplicated as (a,a) pairs
    __shared__ float Bs[8][128];
    int t = threadIdx.x;
    int r0 = blockIdx.y * 128, c0 = blockIdx.x * 128;
    int tx = t & 15, ty = t >> 4;
    int arow = t >> 1, acol = (t & 1) * 4;
    int bk = t >> 5, bc = (t & 31) * 4;

    unsigned long long acc[8][4];
    #pragma unroll
    for (int i = 0; i < 8; i++)
        #pragma unroll
        for (int j = 0; j < 4; j++) acc[i][j] = 0ULL;

    const float* Ap = A + (size_t)(r0 + arow) * K + acol;
    const float* Bp = B + (size_t)bk * M + c0 + bc;

    for (int k0 = 0; k0 < K; k0 += 8) {
        float4 av = *(const float4*)Ap; Ap += 8;
        float4 bv = *(const float4*)Bp; Bp += (size_t)8 * M;
        unsigned int a0 = __float_as_uint(av.x), a1 = __float_as_uint(av.y);
        unsigned int a2 = __float_as_uint(av.z), a3 = __float_as_uint(av.w);
        unsigned long long p;
        asm("mov.b64 %0, {%1,%1};" : "=l"(p) : "r"(a0)); As2[acol + 0][arow] = p;
        asm("mov.b64 %0, {%1,%1};" : "=l"(p) : "r"(a1)); As2[acol + 1][arow] = p;
        asm("mov.b64 %0, {%1,%1};" : "=l"(p) : "r"(a2)); As2[acol + 2][arow] = p;
        asm("mov.b64 %0, {%1,%1};" : "=l"(p) : "r"(a3)); As2[acol + 3][arow] = p;
        *(float4*)&Bs[bk][bc] = bv;
        __syncthreads();
        #pragma unroll
        for (int k = 0; k < 8; k++) {
            const unsigned long long* br = (const unsigned long long*)&Bs[k][tx * 8];
            unsigned long long bp0 = br[0], bp1 = br[1], bp2 = br[2], bp3 = br[3];
            #pragma unroll
            for (int i = 0; i < 8; i++) {
                unsigned long long ap = As2[k][ty * 8 + i];
                asm("fma.rn.f32x2 %0, %1, %2, %0;" : "+l"(acc[i][0]) : "l"(ap), "l"(bp0));
                asm("fma.rn.f32x2 %0, %1, %2, %0;" : "+l"(acc[i][1]) : "l"(ap), "l"(bp1));
                asm("fma.rn.f32x2 %0, %1, %2, %0;" : "+l"(acc[i][2]) : "l"(ap), "l"(bp2));
                asm("fma.rn.f32x2 %0, %1, %2, %0;" : "+l"(acc[i][3]) : "l"(ap), "l"(bp3));
            }
        }
        __syncthreads();
    }

    #pragma unroll
    for (int i = 0; i < 8; i++) {
        int r = r0 + ty * 8 + i;
        float* Cp = C + (size_t)r * M + c0 + tx * 8;
        float v[8];
        #pragma unroll
        for (int j = 0; j < 4; j++) {
            unsigned int lo, hi;
            asm("mov.b64 {%0,%1}, %2;" : "=r"(lo), "=r"(hi) : "l"(acc[i][j]));
            v[2 * j] = __uint_as_float(lo);
            v[2 * j + 1] = __uint_as_float(hi);
        }
        if (bias) {
            #pragma unroll
            for (int j = 0; j < 8; j++) v[j] += bias[c0 + tx * 8 + j];
        }
        if (accumulate) {
            float4 o0 = *(float4*)Cp;
            float4 o1 = *((float4*)Cp + 1);
            v[0] += o0.x; v[1] += o0.y; v[2] += o0.z; v[3] += o0.w;
            v[4] += o1.x; v[5] += o1.y; v[6] += o1.z; v[7] += o1.w;
        }
        *(float4*)Cp = make_float4(v[0], v[1], v[2], v[3]);
        *((float4*)Cp + 1) = make_float4(v[4], v[5], v[6], v[7]);
    }
}

// ---------------- GAT: per-node per-head attention logits ----------------
__global__ void esed_kernel(const float* __restrict__ asrc, const float* __restrict__ adst) {
    int i = blockIdx.x, t = threadIdx.x;   // blockDim = 1024
    float v = g_hgat[(size_t)i * 1024 + t];
    float ps = v * asrc[t], pd = v * adst[t];
    #pragma unroll
    for (int o = 16; o; o >>= 1) {
        ps += __shfl_down_sync(0xffffffffu, ps, o);
        pd += __shfl_down_sync(0xffffffffu, pd, o);
    }
    __shared__ float sp[32], sd[32];
    if ((t & 31) == 0) { sp[t >> 5] = ps; sd[t >> 5] = pd; }
    __syncthreads();
    if (t < 4) {
        float a = 0.f, b = 0.f;
        #pragma unroll
        for (int w = 0; w < 8; w++) { a += sp[t * 8 + w]; b += sd[t * 8 + w]; }
        g_es[i * 4 + t] = a;
        g_ed[i * 4 + t] = b;
    }
}

// ---------------- GAT aggregate: softmax + weighted sum + head mean ----------------
__global__ void gat_agg_kernel(const float* __restrict__ bias) {
    int i = blockIdx.x, t = threadIdx.x;   // blockDim = 256
    int e0 = g_rowptr[i];
    int deg = g_rowptr[i + 1] - e0;
    __shared__ float m[4], z[4];
    __shared__ float alpha[64 * 4];
    int warp = t >> 5, lane = t & 31;

    if (warp < 4) {
        int h = warp;
        float edi = g_ed[i * 4 + h];
        float mx = -1e30f;
        for (int j = lane; j <= deg; j += 32) {
            int s = (j < deg) ? g_csr[e0 + j] : i;
            mx = fmaxf(mx, lrelu(g_es[s * 4 + h] + edi));
        }
        #pragma unroll
        for (int o = 16; o; o >>= 1) mx = fmaxf(mx, __shfl_xor_sync(0xffffffffu, mx, o));
        float zz = 0.f;
        for (int j = lane; j <= deg; j += 32) {
            int s = (j < deg) ? g_csr[e0 + j] : i;
            zz += __expf(lrelu(g_es[s * 4 + h] + edi) - mx);
        }
        #pragma unroll
        for (int o = 16; o; o >>= 1) zz += __shfl_xor_sync(0xffffffffu, zz, o);
        if (lane == 0) { m[h] = mx; z[h] = zz; }
    }
    __syncthreads();

    float acc = 0.f;
    int c = t;
    for (int base = 0; base <= deg; base += 64) {
        int nj = deg + 1 - base; if (nj > 64) nj = 64;
        if (t < nj * 4) {
            int j = t >> 2, h = t & 3;
            int jj = base + j;
            int s = (jj < deg) ? g_csr[e0 + jj] : i;
            float e = lrelu(g_es[s * 4 + h] + g_ed[i * 4 + h]);
            alpha[j * 4 + h] = __expf(e - m[h]) / z[h];
        }
        __syncthreads();
        for (int j = 0; j < nj; j++) {
            int jj = base + j;
            int s = (jj < deg) ? g_csr[e0 + jj] : i;
            const float* hr = g_hgat + (size_t)s * 1024;
            acc += alpha[j * 4 + 0] * hr[c]
                 + alpha[j * 4 + 1] * hr[256 + c]
                 + alpha[j * 4 + 2] * hr[512 + c]
                 + alpha[j * 4 + 3] * hr[768 + c];
        }
        __syncthreads();
    }
    g_bufC[(size_t)i * 256 + c] = acc * 0.25f + bias[c];
}

// ---------------- pooling (mean + max per graph; batch sorted) ----------------
__global__ void pool_kernel() {
    int g = blockIdx.x;
    int c = blockIdx.y * 128 + threadIdx.x;   // 0..511
    int r0 = g_goff[g], r1 = g_goff[g + 1];
    float s = 0.f, mx = -1e30f;
    for (int r = r0; r < r1; r++) {
        float v = g_h4[(size_t)r * 512 + c];
        s += v;
        mx = fmaxf(mx, v);
    }
    int cnt = r1 - r0;
    float mean = s / (float)(cnt > 0 ? cnt : 1);
    if (cnt == 0) mx = 0.f;
    g_pooled[g * 1024 + c] = mean;
    g_pooled[g * 1024 + 512 + c] = mx;
}

// ---------------- final FC: [32,1024] @ [1024,1024] ----------------
__global__ void fc_kernel(const float* __restrict__ w, const float* __restrict__ b,
                          float* __restrict__ out) {
    // grid (8, 4), blockDim 128. Each block: 128 out-cols x 8 graphs.
    int mcol = blockIdx.x * 128 + threadIdx.x;
    int g0 = blockIdx.y * 8;
    float acc[8] = {0, 0, 0, 0, 0, 0, 0, 0};
    __shared__ float sp[8][64];
    for (int k0 = 0; k0 < 1024; k0 += 64) {
        for (int idx = threadIdx.x; idx < 512; idx += 128) {
            int gg = idx >> 6, kk = idx & 63;
            sp[gg][kk] = g_pooled[(g0 + gg) * 1024 + k0 + kk];
        }
        __syncthreads();
        for (int kk = 0; kk < 64; kk++) {
            float wv = w[(size_t)(k0 + kk) * 1024 + mcol];
            #pragma unroll
            for (int gg = 0; gg < 8; gg++) acc[gg] += sp[gg][kk] * wv;
        }
        __syncthreads();
    }
    float bb = b[mcol];
    #pragma unroll
    for (int gg = 0; gg < 8; gg++) out[(g0 + gg) * 1024 + mcol] = acc[gg] + bb;
}

// ---------------- host ----------------
extern "C" void kernel_launch(void* const* d_in, const int* in_sizes, int n_in,
                              void* d_out, int out_size) {
    const float* x        = (const float*)d_in[0];
    const int*   ei       = (const int*)d_in[1];
    const int*   batch    = (const int*)d_in[2];
    const float* gcn1_w   = (const float*)d_in[3];
    const float* gcn1_b   = (const float*)d_in[4];
    const float* sage_wl  = (const float*)d_in[5];
    const float* sage_wr  = (const float*)d_in[6];
    const float* sage_b   = (const float*)d_in[7];
    const float* gat_w    = (const float*)d_in[8];
    const float* gat_asrc = (const float*)d_in[9];
    const float* gat_adst = (const float*)d_in[10];
    const float* gat_b    = (const float*)d_in[11];
    const float* gcn4_w   = (const float*)d_in[12];
    const float* gcn4_b   = (const float*)d_in[13];
    const float* bn1_g    = (const float*)d_in[14];
    const float* bn1_b    = (const float*)d_in[15];
    const float* bn2_g    = (const float*)d_in[16];
    const float* bn2_b    = (const float*)d_in[17];
    const float* bn3_g    = (const float*)d_in[18];
    const float* bn3_b    = (const float*)d_in[19];
    const float* bn4_g    = (const float*)d_in[20];
    const float* bn4_b    = (const float*)d_in[21];
    const float* fc_w     = (const float*)d_in[22];
    const float* fc_b     = (const float*)d_in[23];
    const int* src = ei;
    const int* dst = ei + EE;
    float* out = (float*)d_out;

    // graph structure
    init_kernel<<<64, 256>>>();
    count_kernel<<<(EE + 255) / 256, 256>>>(dst, batch);
    scan_kernel<<<1, 1024>>>();
    fill_csr_kernel<<<(EE + 255) / 256, 256>>>(src, dst);

    // layer 1: GCN(5->64) + BN + ReLU
    lin1_kernel<<<NN, 64>>>(x, gcn1_w);
    gcn_agg_kernel<<<NN, 64>>>(0 /*bufA*/, 1 /*bufB*/, gcn1_b);
    zero_sums_kernel<<<1, 512>>>();
    bn_stats_kernel<<<64, 64>>>(1);
    bn_apply_kernel<<<256, 64>>>(1, 3 /*h1*/, bn1_g, bn1_b);

    // layer 2: SAGE(64->128) + BN + ReLU
    sage_agg_kernel<<<NN, 64>>>();
    sgemm_kernel<<<dim3(1, NN / 128), 256>>>(0 /*bufA*/, sage_wl, 2 /*bufC*/, nullptr, 64, 128, 0);
    sgemm_kernel<<<dim3(1, NN / 128), 256>>>(3 /*h1*/, sage_wr, 2 /*bufC*/, sage_b, 64, 128, 1);
    zero_sums_kernel<<<1, 512>>>();
    bn_stats_kernel<<<64, 128>>>(2);
    bn_apply_kernel<<<256, 128>>>(2, 4 /*h2*/, bn2_g, bn2_b);

    // layer 3: GAT(128->1024, 4 heads of 256, head-mean) + BN + ReLU
    sgemm_kernel<<<dim3(8, NN / 128), 256>>>(4 /*h2*/, gat_w, 8 /*hgat*/, nullptr, 128, 1024, 0);
    esed_kernel<<<NN, 1024>>>(gat_asrc, gat_adst);
    gat_agg_kernel<<<NN, 256>>>(gat_b);
    zero_sums_kernel<<<1, 512>>>();
    bn_stats_kernel<<<64, 256>>>(2);
    bn_apply_kernel<<<256, 256>>>(2, 5 /*h3*/, bn3_g, bn3_b);

    // layer 4: GCN(256->512) + BN + ReLU
    sgemm_kernel<<<dim3(4, NN / 128), 256>>>(5 /*h3*/, gcn4_w, 7 /*h4lin*/, nullptr, 256, 512, 0);
    gcn_agg_kernel<<<NN, 512>>>(7 /*h4lin*/, 1 /*bufB*/, gcn4_b);
    zero_sums_kernel<<<1, 512>>>();
    bn_stats_kernel<<<64, 512>>>(1);
    bn_apply_kernel<<<256, 512>>>(1, 6 /*h4*/, bn4_g, bn4_b);

    // pooling + FC
    pool_kernel<<<dim3(GG, 4), 128>>>();
    fc_kernel<<<dim3(8, 4), 128>>>(fc_w, fc_b, out);
}

// round 8
// speedup vs baseline: 1.4143x; 1.4143x over previous
#include <cuda_runtime.h>

#define NN 16384
#define EE 131072
#define GG 32
#define BN_EPS 1e-5f

// ---------------- scratch (device globals; no allocation APIs) ----------------
__device__ float g_bufA[NN * 64];          // aggx (5-wide) / sage-agg (64-wide)
__device__ float g_bufB[NN * 512];         // pre-BN conv outputs (gcn1, gcn4)
__device__ float g_bufC[NN * 256];         // sage lin (128) / gat out (256)
__device__ float g_h1[NN * 64];
__device__ float g_h2[NN * 128];
__device__ float g_h3[NN * 256];
__device__ float g_h4[NN * 512];
__device__ float g_h4lin[NN * 512];        // layer4 aggregated h3 (256-wide)
__device__ float g_hgat[(long long)NN * 1024];
__device__ float g_es[NN * 4];
__device__ float g_ed[NN * 4];
__device__ float g_dis[NN];
__device__ int   g_indeg[NN];
__device__ int   g_rowptr[NN + 1];
__device__ int   g_cursor[NN];
__device__ int   g_csr[EE];
__device__ int   g_gcnt[GG];
__device__ int   g_goff[GG + 1];
__device__ float g_sum[512];
__device__ float g_sumsq[512];
__device__ float g_pooled[GG * 1024];
__device__ float* g_bp[9];                 // buffer pointer table

__device__ __forceinline__ float lrelu(float x) { return x > 0.f ? x : 0.2f * x; }

// ---------------- setup: counts, pointer table ----------------
__global__ void init_kernel() {
    int idx = blockIdx.x * blockDim.x + threadIdx.x;
    if (idx == 0) {
        g_bp[0] = g_bufA; g_bp[1] = g_bufB; g_bp[2] = g_bufC;
        g_bp[3] = g_h1;   g_bp[4] = g_h2;   g_bp[5] = g_h3;
        g_bp[6] = g_h4;   g_bp[7] = g_h4lin; g_bp[8] = g_hgat;
    }
    if (idx < NN) g_indeg[idx] = 0;
    if (idx < GG) g_gcnt[idx] = 0;
}

__global__ void count_kernel(const int* __restrict__ dst, const int* __restrict__ batch) {
    int idx = blockIdx.x * blockDim.x + threadIdx.x;
    if (idx < EE) atomicAdd(&g_indeg[dst[idx]], 1);
    if (idx < NN) atomicAdd(&g_gcnt[batch[idx]], 1);
}

// single-block exclusive scan of indeg -> rowptr/cursor; also dis and graph offsets
__global__ void scan_kernel() {
    __shared__ int partial[1024];
    int t = threadIdx.x;                 // blockDim = 1024, 16 elems/thread
    int base = t * 16;
    int local[16];
    int s = 0;
    #pragma unroll
    for (int j = 0; j < 16; j++) { local[j] = s; s += g_indeg[base + j]; }
    partial[t] = s;
    __syncthreads();
    for (int off = 1; off < 1024; off <<= 1) {
        int v = (t >= off) ? partial[t - off] : 0;
        __syncthreads();
        partial[t] += v;
        __syncthreads();
    }
    int pre = (t == 0) ? 0 : partial[t - 1];
    #pragma unroll
    for (int j = 0; j < 16; j++) {
        int v = pre + local[j];
        g_rowptr[base + j] = v;
        g_cursor[base + j] = v;
        g_dis[base + j] = rsqrtf((float)(g_indeg[base + j] + 1));
    }
    if (t == 1023) g_rowptr[NN] = partial[1023];
    if (t == 0) {
        int a = 0;
        for (int g = 0; g < GG; g++) { g_goff[g] = a; a += g_gcnt[g]; }
        g_goff[GG] = a;
    }
}

__global__ void fill_csr_kernel(const int* __restrict__ src, const int* __restrict__ dst) {
    int idx = blockIdx.x * blockDim.x + threadIdx.x;
    if (idx < EE) {
        int pos = atomicAdd(&g_cursor[dst[idx]], 1);
        g_csr[pos] = src[idx];
    }
}

// ---------------- layer 1: GCN aggregate on raw x (5-wide) ----------------
__global__ void aggx_kernel(const float* __restrict__ x) {
    int node = blockIdx.x * 32 + (threadIdx.x >> 3);
    int c = threadIdx.x & 7;
    if (c >= 5) return;
    float di = g_dis[node];
    float acc = x[node * 5 + c] * di * di;
    int e0 = g_rowptr[node], e1 = g_rowptr[node + 1];
    for (int e = e0; e < e1; e++) {
        int s = g_csr[e];
        acc += x[s * 5 + c] * (g_dis[s] * di);
    }
    g_bufA[node * 5 + c] = acc;
}

// ---------------- GCN1 linear (K=5 -> 64) with bias ----------------
__global__ void lin1_kernel(const float* __restrict__ w, const float* __restrict__ b) {
    int i = blockIdx.x, c = threadIdx.x;   // blockDim = 64
    float acc = b[c];
    #pragma unroll
    for (int k = 0; k < 5; k++) acc += g_bufA[i * 5 + k] * w[k * 64 + c];
    g_bufB[i * 64 + c] = acc;
}

// ---------------- GCN aggregate (width = blockDim.x), bias optional ----------------
__global__ void gcn_agg_kernel(int insel, int outsel, const float* __restrict__ bias) {
    const float* __restrict__ h = g_bp[insel];
    float* __restrict__ out = g_bp[outsel];
    int W = blockDim.x;
    int i = blockIdx.x, c = threadIdx.x;
    float di = g_dis[i];
    float acc = h[(size_t)i * W + c] * di * di;
    int e0 = g_rowptr[i], e1 = g_rowptr[i + 1];
    for (int e = e0; e < e1; e++) {
        int s = g_csr[e];
        acc += h[(size_t)s * W + c] * (g_dis[s] * di);
    }
    if (bias) acc += bias[c];
    out[(size_t)i * W + c] = acc;
}

// ---------------- SAGE mean aggregate (64-wide, h1 -> bufA) ----------------
__global__ void sage_agg_kernel() {
    int i = blockIdx.x, c = threadIdx.x;   // blockDim = 64
    int e0 = g_rowptr[i], e1 = g_rowptr[i + 1];
    float acc = 0.f;
    for (int e = e0; e < e1; e++) acc += g_h1[(size_t)g_csr[e] * 64 + c];
    int cnt = e1 - e0;
    g_bufA[i * 64 + c] = acc / (float)(cnt > 0 ? cnt : 1);
}

// ---------------- BN stats / apply (width = blockDim.x) ----------------
__global__ void zero_sums_kernel() { g_sum[threadIdx.x] = 0.f; g_sumsq[threadIdx.x] = 0.f; }

__global__ void bn_stats_kernel(int insel) {
    const float* __restrict__ h = g_bp[insel];
    int W = blockDim.x, c = threadIdx.x;
    float s = 0.f, s2 = 0.f;
    for (int r = blockIdx.x; r < NN; r += gridDim.x) {
        float v = h[(size_t)r * W + c];
        s += v; s2 += v * v;
    }
    atomicAdd(&g_sum[c], s);
    atomicAdd(&g_sumsq[c], s2);
}

__global__ void bn_apply_kernel(int insel, int outsel,
                                const float* __restrict__ gam, const float* __restrict__ bet) {
    const float* __restrict__ h = g_bp[insel];
    float* __restrict__ out = g_bp[outsel];
    int W = blockDim.x, c = threadIdx.x;
    float mean = g_sum[c] * (1.f / NN);
    float var = g_sumsq[c] * (1.f / NN) - mean * mean;
    float sc = gam[c] * rsqrtf(var + BN_EPS);
    float sh = bet[c] - mean * sc;
    for (int r = blockIdx.x; r < NN; r += gridDim.x) {
        float v = h[(size_t)r * W + c] * sc + sh;
        out[(size_t)r * W + c] = fmaxf(v, 0.f);
    }
}

// ---------------- SGEMM: C[NN,M] = A1[NN,K1]@B1 (+ A2[NN,K2]@B2) + bias ----------------
// Double-buffered smem, f32x2 packed FMA, conflict-free B reads.
// Thread t: tx = t&15 owns cols {c0 + tx*2 + j*32 : j=0..3}; ty = t>>4 owns rows ty*8..ty*8+7.
__global__ __launch_bounds__(256)
void sgemm_kernel(int a1sel, const float* __restrict__ B1,
                  int a2sel, const float* __restrict__ B2,
                  int csel, const float* __restrict__ bias,
                  int K1, int K2, int M) {
    const float* __restrict__ A1 = g_bp[a1sel];
    const float* __restrict__ A2 = (a2sel >= 0) ? g_bp[a2sel] : (const float*)0;
    float* __restrict__ C = g_bp[csel];
    __shared__ unsigned long long As2[2][8][128];   // A pre-duplicated (a,a) pairs
    __shared__ float Bs[2][8][128];

    int t = threadIdx.x;
    int r0 = blockIdx.y * 128, c0 = blockIdx.x * 128;
    int tx = t & 15, ty = t >> 4;
    int arow = t >> 1, acol = (t & 1) * 4;     // A: row arow, k-offset acol..acol+3
    int bk = t >> 5, bc = (t & 31) * 4;        // B: k-row bk, col bc..bc+3

    int T1 = K1 / 8;
    int T = T1 + ((a2sel >= 0) ? (K2 / 8) : 0);

    unsigned long long acc[8][4];
    #pragma unroll
    for (int i = 0; i < 8; i++)
        #pragma unroll
        for (int j = 0; j < 4; j++) acc[i][j] = 0ULL;

    // prologue: load tile 0
    float4 av, bv;
    {
        const float* Ap = A1 + (size_t)(r0 + arow) * K1 + acol;
        const float* Bp = B1 + (size_t)bk * M + c0 + bc;
        av = *(const float4*)Ap;
        bv = *(const float4*)Bp;
    }
    int buf = 0;
    {
        unsigned int a0 = __float_as_uint(av.x), a1 = __float_as_uint(av.y);
        unsigned int a2 = __float_as_uint(av.z), a3 = __float_as_uint(av.w);
        unsigned long long p;
        asm("mov.b64 %0, {%1,%1};" : "=l"(p) : "r"(a0)); As2[0][acol + 0][arow] = p;
        asm("mov.b64 %0, {%1,%1};" : "=l"(p) : "r"(a1)); As2[0][acol + 1][arow] = p;
        asm("mov.b64 %0, {%1,%1};" : "=l"(p) : "r"(a2)); As2[0][acol + 2][arow] = p;
        asm("mov.b64 %0, {%1,%1};" : "=l"(p) : "r"(a3)); As2[0][acol + 3][arow] = p;
        *(float4*)&Bs[0][bk][bc] = bv;
    }
    __syncthreads();

    for (int tt = 0; tt < T; tt++) {
        // prefetch tile tt+1 into registers (overlaps compute)
        if (tt + 1 < T) {
            int nt = tt + 1;
            const float* Ap;
            const float* Bp;
            if (nt < T1) {
                Ap = A1 + (size_t)(r0 + arow) * K1 + nt * 8 + acol;
                Bp = B1 + (size_t)(nt * 8 + bk) * M + c0 + bc;
            } else {
                int mt = nt - T1;
                Ap = A2 + (size_t)(r0 + arow) * K2 + mt * 8 + acol;
                Bp = B2 + (size_t)(mt * 8 + bk) * M + c0 + bc;
            }
            av = *(const float4*)Ap;
            bv = *(const float4*)Bp;
        }

        // compute current buffer
        #pragma unroll
        for (int k = 0; k < 8; k++) {
            const unsigned long long* brow = (const unsigned long long*)&Bs[buf][k][0];
            unsigned long long bp0 = brow[tx];
            unsigned long long bp1 = brow[tx + 16];
            unsigned long long bp2 = brow[tx + 32];
            unsigned long long bp3 = brow[tx + 48];
            #pragma unroll
            for (int i = 0; i < 8; i++) {
                unsigned long long ap = As2[buf][k][ty * 8 + i];
                asm("fma.rn.f32x2 %0, %1, %2, %0;" : "+l"(acc[i][0]) : "l"(ap), "l"(bp0));
                asm("fma.rn.f32x2 %0, %1, %2, %0;" : "+l"(acc[i][1]) : "l"(ap), "l"(bp1));
                asm("fma.rn.f32x2 %0, %1, %2, %0;" : "+l"(acc[i][2]) : "l"(ap), "l"(bp2));
                asm("fma.rn.f32x2 %0, %1, %2, %0;" : "+l"(acc[i][3]) : "l"(ap), "l"(bp3));
            }
        }

        // stage tile tt+1 into the other buffer (no race: other buffer)
        if (tt + 1 < T) {
            int nb = buf ^ 1;
            unsigned int a0 = __float_as_uint(av.x), a1 = __float_as_uint(av.y);
            unsigned int a2 = __float_as_uint(av.z), a3 = __float_as_uint(av.w);
            unsigned long long p;
            asm("mov.b64 %0, {%1,%1};" : "=l"(p) : "r"(a0)); As2[nb][acol + 0][arow] = p;
            asm("mov.b64 %0, {%1,%1};" : "=l"(p) : "r"(a1)); As2[nb][acol + 1][arow] = p;
            asm("mov.b64 %0, {%1,%1};" : "=l"(p) : "r"(a2)); As2[nb][acol + 2][arow] = p;
            asm("mov.b64 %0, {%1,%1};" : "=l"(p) : "r"(a3)); As2[nb][acol + 3][arow] = p;
            *(float4*)&Bs[nb][bk][bc] = bv;
        }
        __syncthreads();
        buf ^= 1;
    }

    // epilogue: cols c0 + tx*2 + j*32
    float2 bb[4];
    if (bias) {
        const float2* bp2 = (const float2*)(bias + c0);
        #pragma unroll
        for (int j = 0; j < 4; j++) bb[j] = bp2[tx + j * 16];
    } else {
        #pragma unroll
        for (int j = 0; j < 4; j++) bb[j] = make_float2(0.f, 0.f);
    }
    #pragma unroll
    for (int i = 0; i < 8; i++) {
        int r = r0 + ty * 8 + i;
        float2* Cp = (float2*)(C + (size_t)r * M + c0) + tx;
        #pragma unroll
        for (int j = 0; j < 4; j++) {
            unsigned int lo, hi;
            asm("mov.b64 {%0,%1}, %2;" : "=r"(lo), "=r"(hi) : "l"(acc[i][j]));
            Cp[j * 16] = make_float2(__uint_as_float(lo) + bb[j].x,
                                     __uint_as_float(hi) + bb[j].y);
        }
    }
}

// ---------------- GAT: per-node per-head attention logits ----------------
__global__ void esed_kernel(const float* __restrict__ asrc, const float* __restrict__ adst) {
    int i = blockIdx.x, t = threadIdx.x;   // blockDim = 1024
    float v = g_hgat[(size_t)i * 1024 + t];
    float ps = v * asrc[t], pd = v * adst[t];
    #pragma unroll
    for (int o = 16; o; o >>= 1) {
        ps += __shfl_down_sync(0xffffffffu, ps, o);
        pd += __shfl_down_sync(0xffffffffu, pd, o);
    }
    __shared__ float sp[32], sd[32];
    if ((t & 31) == 0) { sp[t >> 5] = ps; sd[t >> 5] = pd; }
    __syncthreads();
    if (t < 4) {
        float a = 0.f, b = 0.f;
        #pragma unroll
        for (int w = 0; w < 8; w++) { a += sp[t * 8 + w]; b += sd[t * 8 + w]; }
        g_es[i * 4 + t] = a;
        g_ed[i * 4 + t] = b;
    }
}

// ---------------- GAT aggregate: softmax + weighted sum + head mean ----------------
__global__ void gat_agg_kernel(const float* __restrict__ bias) {
    int i = blockIdx.x, t = threadIdx.x;   // blockDim = 256
    int e0 = g_rowptr[i];
    int deg = g_rowptr[i + 1] - e0;
    __shared__ float m[4], z[4];
    __shared__ float alpha[64 * 4];
    int warp = t >> 5, lane = t & 31;

    if (warp < 4) {
        int h = warp;
        float edi = g_ed[i * 4 + h];
        float mx = -1e30f;
        for (int j = lane; j <= deg; j += 32) {
            int s = (j < deg) ? g_csr[e0 + j] : i;
            mx = fmaxf(mx, lrelu(g_es[s * 4 + h] + edi));
        }
        #pragma unroll
        for (int o = 16; o; o >>= 1) mx = fmaxf(mx, __shfl_xor_sync(0xffffffffu, mx, o));
        float zz = 0.f;
        for (int j = lane; j <= deg; j += 32) {
            int s = (j < deg) ? g_csr[e0 + j] : i;
            zz += __expf(lrelu(g_es[s * 4 + h] + edi) - mx);
        }
        #pragma unroll
        for (int o = 16; o; o >>= 1) zz += __shfl_xor_sync(0xffffffffu, zz, o);
        if (lane == 0) { m[h] = mx; z[h] = zz; }
    }
    __syncthreads();

    float acc = 0.f;
    int c = t;
    for (int base = 0; base <= deg; base += 64) {
        int nj = deg + 1 - base; if (nj > 64) nj = 64;
        if (t < nj * 4) {
            int j = t >> 2, h = t & 3;
            int jj = base + j;
            int s = (jj < deg) ? g_csr[e0 + jj] : i;
            float e = lrelu(g_es[s * 4 + h] + g_ed[i * 4 + h]);
            alpha[j * 4 + h] = __expf(e - m[h]) / z[h];
        }
        __syncthreads();
        for (int j = 0; j < nj; j++) {
            int jj = base + j;
            int s = (jj < deg) ? g_csr[e0 + jj] : i;
            const float* hr = g_hgat + (size_t)s * 1024;
            acc += alpha[j * 4 + 0] * hr[c]
                 + alpha[j * 4 + 1] * hr[256 + c]
                 + alpha[j * 4 + 2] * hr[512 + c]
                 + alpha[j * 4 + 3] * hr[768 + c];
        }
        __syncthreads();
    }
    g_bufC[(size_t)i * 256 + c] = acc * 0.25f + bias[c];
}

// ---------------- pooling (mean + max per graph; batch sorted) ----------------
__global__ void pool_kernel() {
    int g = blockIdx.x;
    int c = blockIdx.y * 128 + threadIdx.x;   // 0..511
    int r0 = g_goff[g], r1 = g_goff[g + 1];
    float s = 0.f, mx = -1e30f;
    for (int r = r0; r < r1; r++) {
        float v = g_h4[(size_t)r * 512 + c];
        s += v;
        mx = fmaxf(mx, v);
    }
    int cnt = r1 - r0;
    float mean = s / (float)(cnt > 0 ? cnt : 1);
    if (cnt == 0) mx = 0.f;
    g_pooled[g * 1024 + c] = mean;
    g_pooled[g * 1024 + 512 + c] = mx;
}

// ---------------- final FC: [32,1024] @ [1024,1024] ----------------
__global__ void fc_kernel(const float* __restrict__ w, const float* __restrict__ b,
                          float* __restrict__ out) {
    int mcol = blockIdx.x * 128 + threadIdx.x;
    int g0 = blockIdx.y * 8;
    float acc[8] = {0, 0, 0, 0, 0, 0, 0, 0};
    __shared__ float sp[8][64];
    for (int k0 = 0; k0 < 1024; k0 += 64) {
        for (int idx = threadIdx.x; idx < 512; idx += 128) {
            int gg = idx >> 6, kk = idx & 63;
            sp[gg][kk] = g_pooled[(g0 + gg) * 1024 + k0 + kk];
        }
        __syncthreads();
        for (int kk = 0; kk < 64; kk++) {
            float wv = w[(size_t)(k0 + kk) * 1024 + mcol];
            #pragma unroll
            for (int gg = 0; gg < 8; gg++) acc[gg] += sp[gg][kk] * wv;
        }
        __syncthreads();
    }
    float bb = b[mcol];
    #pragma unroll
    for (int gg = 0; gg < 8; gg++) out[(g0 + gg) * 1024 + mcol] = acc[gg] + bb;
}

// ---------------- host ----------------
extern "C" void kernel_launch(void* const* d_in, const int* in_sizes, int n_in,
                              void* d_out, int out_size) {
    const float* x        = (const float*)d_in[0];
    const int*   ei       = (const int*)d_in[1];
    const int*   batch    = (const int*)d_in[2];
    const float* gcn1_w   = (const float*)d_in[3];
    const float* gcn1_b   = (const float*)d_in[4];
    const float* sage_wl  = (const float*)d_in[5];
    const float* sage_wr  = (const float*)d_in[6];
    const float* sage_b   = (const float*)d_in[7];
    const float* gat_w    = (const float*)d_in[8];
    const float* gat_asrc = (const float*)d_in[9];
    const float* gat_adst = (const float*)d_in[10];
    const float* gat_b    = (const float*)d_in[11];
    const float* gcn4_w   = (const float*)d_in[12];
    const float* gcn4_b   = (const float*)d_in[13];
    const float* bn1_g    = (const float*)d_in[14];
    const float* bn1_b    = (const float*)d_in[15];
    const float* bn2_g    = (const float*)d_in[16];
    const float* bn2_b    = (const float*)d_in[17];
    const float* bn3_g    = (const float*)d_in[18];
    const float* bn3_b    = (const float*)d_in[19];
    const float* bn4_g    = (const float*)d_in[20];
    const float* bn4_b    = (const float*)d_in[21];
    const float* fc_w     = (const float*)d_in[22];
    const float* fc_b     = (const float*)d_in[23];
    const int* src = ei;
    const int* dst = ei + EE;
    float* out = (float*)d_out;

    // graph structure
    init_kernel<<<64, 256>>>();
    count_kernel<<<(EE + 255) / 256, 256>>>(dst, batch);
    scan_kernel<<<1, 1024>>>();
    fill_csr_kernel<<<(EE + 255) / 256, 256>>>(src, dst);

    // layer 1: GCN(5->64) + BN + ReLU   (aggregate-then-linear: GCN is linear in x)
    aggx_kernel<<<NN / 32, 256>>>(x);
    lin1_kernel<<<NN, 64>>>(gcn1_w, gcn1_b);              // -> bufB (pre-BN)
    zero_sums_kernel<<<1, 512>>>();
    bn_stats_kernel<<<256, 64>>>(1);
    bn_apply_kernel<<<256, 64>>>(1, 3 /*h1*/, bn1_g, bn1_b);

    // layer 2: SAGE(64->128) + BN + ReLU   (fused dual GEMM: agg@wl + h1@wr + b)
    sage_agg_kernel<<<NN, 64>>>();                        // -> bufA
    sgemm_kernel<<<dim3(1, NN / 128), 256>>>(0, sage_wl, 3, sage_wr,
                                             2 /*bufC*/, sage_b, 64, 64, 128);
    zero_sums_kernel<<<1, 512>>>();
    bn_stats_kernel<<<256, 128>>>(2);
    bn_apply_kernel<<<256, 128>>>(2, 4 /*h2*/, bn2_g, bn2_b);

    // layer 3: GAT(128->1024, 4 heads of 256, head-mean) + BN + ReLU
    sgemm_kernel<<<dim3(8, NN / 128), 256>>>(4, gat_w, -1, nullptr,
                                             8 /*hgat*/, nullptr, 128, 0, 1024);
    esed_kernel<<<NN, 1024>>>(gat_asrc, gat_adst);
    gat_agg_kernel<<<NN, 256>>>(gat_b);                   // -> bufC (pre-BN)
    zero_sums_kernel<<<1, 512>>>();
    bn_stats_kernel<<<256, 256>>>(2);
    bn_apply_kernel<<<256, 256>>>(2, 5 /*h3*/, bn3_g, bn3_b);

    // layer 4: GCN(256->512) + BN + ReLU   (aggregate h3 first, then GEMM)
    gcn_agg_kernel<<<NN, 256>>>(5 /*h3*/, 7 /*h4lin*/, nullptr);
    sgemm_kernel<<<dim3(4, NN / 128), 256>>>(7, gcn4_w, -1, nullptr,
                                             1 /*bufB*/, gcn4_b, 256, 0, 512);
    zero_sums_kernel<<<1, 512>>>();
    bn_stats_kernel<<<256, 512>>>(1);
    bn_apply_kernel<<<256, 512>>>(1, 6 /*h4*/, bn4_g, bn4_b);

    // pooling + FC
    pool_kernel<<<dim3(GG, 4), 128>>>();
    fc_kernel<<<dim3(8, 4), 128>>>(fc_w, fc_b, out);
}

// round 13
// speedup vs baseline: 1.4444x; 1.0213x over previous
#include <cuda_runtime.h>
#include <cstdint>

#define NN 16384
#define EE 131072
#define GG 32
#define BN_EPS 1e-5f

// ---------------- scratch (device globals; no allocation APIs) ----------------
__device__ float g_bufA[NN * 64];          // aggx (5-wide) / sage-agg (64-wide)
__device__ float g_bufB[NN * 512];         // lin1 out (64) / gcn4 gemm out (512)
__device__ float g_bufC[NN * 256];         // sage lin out (128) / gat out (256)
__device__ float g_h1[NN * 64];
__device__ float g_h2[NN * 128];
__device__ float g_h4lin[NN * 256];        // layer4 aggregated BN3(h) (256-wide)
__device__ float g_hgat[(long long)NN * 1024];
__device__ float g_es[NN * 4];
__device__ float g_ed[NN * 4];
__device__ float g_dis[NN];
__device__ int   g_indeg[NN];
__device__ int   g_rowptr[NN + 1];
__device__ int   g_cursor[NN];
__device__ int   g_csr[EE];
__device__ int   g_gcnt[GG];
__device__ int   g_goff[GG + 1];
__device__ float g_sum[4 * 512];
__device__ float g_sumsq[4 * 512];
__device__ float g_pooled[GG * 1024];
__device__ float* g_bp[7];                 // buffer pointer table

__device__ __forceinline__ float lrelu(float x) { return x > 0.f ? x : 0.2f * x; }

// ---------------- setup: counts, sums, pointer table ----------------
__global__ void init_kernel() {
    int idx = blockIdx.x * blockDim.x + threadIdx.x;
    if (idx == 0) {
        g_bp[0] = g_bufA; g_bp[1] = g_bufB; g_bp[2] = g_bufC;
        g_bp[3] = g_h1;   g_bp[4] = g_h2;   g_bp[5] = g_h4lin;
        g_bp[6] = g_hgat;
    }
    if (idx < NN) g_indeg[idx] = 0;
    if (idx < GG) g_gcnt[idx] = 0;
    if (idx < 4 * 512) { g_sum[idx] = 0.f; g_sumsq[idx] = 0.f; }
}

__global__ void count_kernel(const int* __restrict__ dst, const int* __restrict__ batch) {
    int idx = blockIdx.x * blockDim.x + threadIdx.x;
    if (idx < EE) atomicAdd(&g_indeg[dst[idx]], 1);
    if (idx < NN) atomicAdd(&g_gcnt[batch[idx]], 1);
}

// single-block exclusive scan of indeg -> rowptr/cursor; also dis and graph offsets
__global__ void scan_kernel() {
    __shared__ int partial[1024];
    int t = threadIdx.x;                 // blockDim = 1024, 16 elems/thread
    int base = t * 16;
    int local[16];
    int s = 0;
    #pragma unroll
    for (int j = 0; j < 16; j++) { local[j] = s; s += g_indeg[base + j]; }
    partial[t] = s;
    __syncthreads();
    for (int off = 1; off < 1024; off <<= 1) {
        int v = (t >= off) ? partial[t - off] : 0;
        __syncthreads();
        partial[t] += v;
        __syncthreads();
    }
    int pre = (t == 0) ? 0 : partial[t - 1];
    #pragma unroll
    for (int j = 0; j < 16; j++) {
        int v = pre + local[j];
        g_rowptr[base + j] = v;
        g_cursor[base + j] = v;
        g_dis[base + j] = rsqrtf((float)(g_indeg[base + j] + 1));
    }
    if (t == 1023) g_rowptr[NN] = partial[1023];
    if (t == 0) {
        int a = 0;
        for (int g = 0; g < GG; g++) { g_goff[g] = a; a += g_gcnt[g]; }
        g_goff[GG] = a;
    }
}

__global__ void fill_csr_kernel(const int* __restrict__ src, const int* __restrict__ dst) {
    int idx = blockIdx.x * blockDim.x + threadIdx.x;
    if (idx < EE) {
        int pos = atomicAdd(&g_cursor[dst[idx]], 1);
        g_csr[pos] = src[idx];
    }
}

// ---------------- layer 1: GCN aggregate on raw x (5-wide) ----------------
__global__ void aggx_kernel(const float* __restrict__ x) {
    int node = blockIdx.x * 32 + (threadIdx.x >> 3);
    int c = threadIdx.x & 7;
    if (c >= 5) return;
    float di = g_dis[node];
    float acc = x[node * 5 + c] * di * di;
    int e0 = g_rowptr[node], e1 = g_rowptr[node + 1];
    for (int e = e0; e < e1; e++) {
        int s = g_csr[e];
        acc += x[s * 5 + c] * (g_dis[s] * di);
    }
    g_bufA[node * 5 + c] = acc;
}

// ---------------- GCN1 linear (K=5 -> 64) with bias ----------------
__global__ void lin1_kernel(const float* __restrict__ w, const float* __restrict__ b) {
    int i = blockIdx.x, c = threadIdx.x;   // blockDim = 64
    float acc = b[c];
    #pragma unroll
    for (int k = 0; k < 5; k++) acc += g_bufA[i * 5 + k] * w[k * 64 + c];
    g_bufB[i * 64 + c] = acc;
}

// ---------------- SAGE mean aggregate (64-wide, h1 -> bufA) ----------------
__global__ void sage_agg_kernel() {
    int i = blockIdx.x, c = threadIdx.x;   // blockDim = 64
    int e0 = g_rowptr[i], e1 = g_rowptr[i + 1];
    float acc = 0.f;
    for (int e = e0; e < e1; e++) acc += g_h1[(size_t)g_csr[e] * 64 + c];
    int cnt = e1 - e0;
    g_bufA[i * 64 + c] = acc / (float)(cnt > 0 ? cnt : 1);
}

// ---------------- BN stats / apply (width = blockDim.x) ----------------
__global__ void bn_stats_kernel(int insel, int layer) {
    const float* __restrict__ h = g_bp[insel];
    int W = blockDim.x, c = threadIdx.x;
    float s = 0.f, s2 = 0.f;
    for (int r = blockIdx.x; r < NN; r += gridDim.x) {
        float v = h[(size_t)r * W + c];
        s += v; s2 += v * v;
    }
    atomicAdd(&g_sum[layer * 512 + c], s);
    atomicAdd(&g_sumsq[layer * 512 + c], s2);
}

__global__ void bn_apply_kernel(int insel, int outsel, int layer,
                                const float* __restrict__ gam, const float* __restrict__ bet) {
    const float* __restrict__ h = g_bp[insel];
    float* __restrict__ out = g_bp[outsel];
    int W = blockDim.x, c = threadIdx.x;
    float mean = g_sum[layer * 512 + c] * (1.f / NN);
    float var = g_sumsq[layer * 512 + c] * (1.f / NN) - mean * mean;
    float sc = gam[c] * rsqrtf(var + BN_EPS);
    float sh = bet[c] - mean * sc;
    for (int r = blockIdx.x; r < NN; r += gridDim.x) {
        float v = h[(size_t)r * W + c] * sc + sh;
        out[(size_t)r * W + c] = fmaxf(v, 0.f);
    }
}

// ---------------- SGEMM: C[NN,M] = A1[NN,K1]@B1 (+ A2[NN,K2]@B2) + bias ----------------
// Double-buffered smem, f32x2 packed FMA, conflict-free B reads.
// Thread t: tx = t&15 owns cols {c0 + tx*2 + j*32 : j=0..3}; ty = t>>4 owns rows ty*8..ty*8+7.
__global__ __launch_bounds__(256)
void sgemm_kernel(int a1sel, const float* __restrict__ B1,
                  int a2sel, const float* __restrict__ B2,
                  int csel, const float* __restrict__ bias,
                  int K1, int K2, int M) {
    const float* __restrict__ A1 = g_bp[a1sel];
    const float* __restrict__ A2 = (a2sel >= 0) ? g_bp[a2sel] : (const float*)0;
    float* __restrict__ C = g_bp[csel];
    __shared__ unsigned long long As2[2][8][128];   // A pre-duplicated (a,a) pairs
    __shared__ float Bs[2][8][128];

    int t = threadIdx.x;
    int r0 = blockIdx.y * 128, c0 = blockIdx.x * 128;
    int tx = t & 15, ty = t >> 4;
    int arow = t >> 1, acol = (t & 1) * 4;     // A: row arow, k-offset acol..acol+3
    int bk = t >> 5, bc = (t & 31) * 4;        // B: k-row bk, col bc..bc+3

    int T1 = K1 / 8;
    int T = T1 + ((a2sel >= 0) ? (K2 / 8) : 0);

    unsigned long long acc[8][4];
    #pragma unroll
    for (int i = 0; i < 8; i++)
        #pragma unroll
        for (int j = 0; j < 4; j++) acc[i][j] = 0ULL;

    float4 av, bv;
    {
        const float* Ap = A1 + (size_t)(r0 + arow) * K1 + acol;
        const float* Bp = B1 + (size_t)bk * M + c0 + bc;
        av = *(const float4*)Ap;
        bv = *(const float4*)Bp;
    }
    int buf = 0;
    {
        unsigned int a0 = __float_as_uint(av.x), a1 = __float_as_uint(av.y);
        unsigned int a2 = __float_as_uint(av.z), a3 = __float_as_uint(av.w);
        unsigned long long p;
        asm("mov.b64 %0, {%1,%1};" : "=l"(p) : "r"(a0)); As2[0][acol + 0][arow] = p;
        asm("mov.b64 %0, {%1,%1};" : "=l"(p) : "r"(a1)); As2[0][acol + 1][arow] = p;
        asm("mov.b64 %0, {%1,%1};" : "=l"(p) : "r"(a2)); As2[0][acol + 2][arow] = p;
        asm("mov.b64 %0, {%1,%1};" : "=l"(p) : "r"(a3)); As2[0][acol + 3][arow] = p;
        *(float4*)&Bs[0][bk][bc] = bv;
    }
    __syncthreads();

    for (int tt = 0; tt < T; tt++) {
        if (tt + 1 < T) {
            int nt = tt + 1;
            const float* Ap;
            const float* Bp;
            if (nt < T1) {
                Ap = A1 + (size_t)(r0 + arow) * K1 + nt * 8 + acol;
                Bp = B1 + (size_t)(nt * 8 + bk) * M + c0 + bc;
            } else {
                int mt = nt - T1;
                Ap = A2 + (size_t)(r0 + arow) * K2 + mt * 8 + acol;
                Bp = B2 + (size_t)(mt * 8 + bk) * M + c0 + bc;
            }
            av = *(const float4*)Ap;
            bv = *(const float4*)Bp;
        }

        #pragma unroll
        for (int k = 0; k < 8; k++) {
            const unsigned long long* brow = (const unsigned long long*)&Bs[buf][k][0];
            unsigned long long bp0 = brow[tx];
            unsigned long long bp1 = brow[tx + 16];
            unsigned long long bp2 = brow[tx + 32];
            unsigned long long bp3 = brow[tx + 48];
            #pragma unroll
            for (int i = 0; i < 8; i++) {
                unsigned long long ap = As2[buf][k][ty * 8 + i];
                asm("fma.rn.f32x2 %0, %1, %2, %0;" : "+l"(acc[i][0]) : "l"(ap), "l"(bp0));
                asm("fma.rn.f32x2 %0, %1, %2, %0;" : "+l"(acc[i][1]) : "l"(ap), "l"(bp1));
                asm("fma.rn.f32x2 %0, %1, %2, %0;" : "+l"(acc[i][2]) : "l"(ap), "l"(bp2));
                asm("fma.rn.f32x2 %0, %1, %2, %0;" : "+l"(acc[i][3]) : "l"(ap), "l"(bp3));
            }
        }

        if (tt + 1 < T) {
            int nb = buf ^ 1;
            unsigned int a0 = __float_as_uint(av.x), a1 = __float_as_uint(av.y);
            unsigned int a2 = __float_as_uint(av.z), a3 = __float_as_uint(av.w);
            unsigned long long p;
            asm("mov.b64 %0, {%1,%1};" : "=l"(p) : "r"(a0)); As2[nb][acol + 0][arow] = p;
            asm("mov.b64 %0, {%1,%1};" : "=l"(p) : "r"(a1)); As2[nb][acol + 1][arow] = p;
            asm("mov.b64 %0, {%1,%1};" : "=l"(p) : "r"(a2)); As2[nb][acol + 2][arow] = p;
            asm("mov.b64 %0, {%1,%1};" : "=l"(p) : "r"(a3)); As2[nb][acol + 3][arow] = p;
            *(float4*)&Bs[nb][bk][bc] = bv;
        }
        __syncthreads();
        buf ^= 1;
    }

    // epilogue: cols c0 + tx*2 + j*32
    float2 bb[4];
    if (bias) {
        const float2* bp2 = (const float2*)(bias + c0);
        #pragma unroll
        for (int j = 0; j < 4; j++) bb[j] = bp2[tx + j * 16];
    } else {
        #pragma unroll
        for (int j = 0; j < 4; j++) bb[j] = make_float2(0.f, 0.f);
    }
    #pragma unroll
    for (int i = 0; i < 8; i++) {
        int r = r0 + ty * 8 + i;
        float2* Cp = (float2*)(C + (size_t)r * M + c0) + tx;
        #pragma unroll
        for (int j = 0; j < 4; j++) {
            unsigned int lo, hi;
            asm("mov.b64 {%0,%1}, %2;" : "=r"(lo), "=r"(hi) : "l"(acc[i][j]));
            Cp[j * 16] = make_float2(__uint_as_float(lo) + bb[j].x,
                                     __uint_as_float(hi) + bb[j].y);
        }
    }
}

// ---------------- GAT: per-node per-head attention logits ----------------
__global__ void esed_kernel(const float* __restrict__ asrc, const float* __restrict__ adst) {
    int i = blockIdx.x, t = threadIdx.x;   // blockDim = 1024
    float v = g_hgat[(size_t)i * 1024 + t];
    float ps = v * asrc[t], pd = v * adst[t];
    #pragma unroll
    for (int o = 16; o; o >>= 1) {
        ps += __shfl_down_sync(0xffffffffu, ps, o);
        pd += __shfl_down_sync(0xffffffffu, pd, o);
    }
    __shared__ float sp[32], sd[32];
    if ((t & 31) == 0) { sp[t >> 5] = ps; sd[t >> 5] = pd; }
    __syncthreads();
    if (t < 4) {
        float a = 0.f, b = 0.f;
        #pragma unroll
        for (int w = 0; w < 8; w++) { a += sp[t * 8 + w]; b += sd[t * 8 + w]; }
        g_es[i * 4 + t] = a;
        g_ed[i * 4 + t] = b;
    }
}

// ---------------- GAT aggregate: softmax + weighted sum + head mean ----------------
__global__ void gat_agg_kernel(const float* __restrict__ bias) {
    int i = blockIdx.x, t = threadIdx.x;   // blockDim = 256
    int e0 = g_rowptr[i];
    int deg = g_rowptr[i + 1] - e0;
    __shared__ float m[4], z[4];
    __shared__ float alpha[64 * 4];
    int warp = t >> 5, lane = t & 31;

    if (warp < 4) {
        int h = warp;
        float edi = g_ed[i * 4 + h];
        float mx = -1e30f;
        for (int j = lane; j <= deg; j += 32) {
            int s = (j < deg) ? g_csr[e0 + j] : i;
            mx = fmaxf(mx, lrelu(g_es[s * 4 + h] + edi));
        }
        #pragma unroll
        for (int o = 16; o; o >>= 1) mx = fmaxf(mx, __shfl_xor_sync(0xffffffffu, mx, o));
        float zz = 0.f;
        for (int j = lane; j <= deg; j += 32) {
            int s = (j < deg) ? g_csr[e0 + j] : i;
            zz += __expf(lrelu(g_es[s * 4 + h] + edi) - mx);
        }
        #pragma unroll
        for (int o = 16; o; o >>= 1) zz += __shfl_xor_sync(0xffffffffu, zz, o);
        if (lane == 0) { m[h] = mx; z[h] = zz; }
    }
    __syncthreads();

    float acc = 0.f;
    int c = t;
    for (int base = 0; base <= deg; base += 64) {
        int nj = deg + 1 - base; if (nj > 64) nj = 64;
        if (t < nj * 4) {
            int j = t >> 2, h = t & 3;
            int jj = base + j;
            int s = (jj < deg) ? g_csr[e0 + jj] : i;
            float e = lrelu(g_es[s * 4 + h] + g_ed[i * 4 + h]);
            alpha[j * 4 + h] = __expf(e - m[h]) / z[h];
        }
        __syncthreads();
        for (int j = 0; j < nj; j++) {
            int jj = base + j;
            int s = (jj < deg) ? g_csr[e0 + jj] : i;
            const float* hr = g_hgat + (size_t)s * 1024;
            acc += alpha[j * 4 + 0] * hr[c]
                 + alpha[j * 4 + 1] * hr[256 + c]
                 + alpha[j * 4 + 2] * hr[512 + c]
                 + alpha[j * 4 + 3] * hr[768 + c];
        }
        __syncthreads();
    }
    g_bufC[(size_t)i * 256 + c] = acc * 0.25f + bias[c];
}

// ---------------- layer 4 aggregate with fused BN3 + relu (bufC -> h4lin) ----------------
__global__ void gcn_agg_bn_kernel(const float* __restrict__ gam, const float* __restrict__ bet) {
    int i = blockIdx.x, c = threadIdx.x;   // blockDim = 256
    float mean = g_sum[2 * 512 + c] * (1.f / NN);
    float var = g_sumsq[2 * 512 + c] * (1.f / NN) - mean * mean;
    float sc = gam[c] * rsqrtf(var + BN_EPS);
    float sh = bet[c] - mean * sc;
    float di = g_dis[i];
    float acc = fmaxf(g_bufC[(size_t)i * 256 + c] * sc + sh, 0.f) * di * di;
    int e0 = g_rowptr[i], e1 = g_rowptr[i + 1];
    for (int e = e0; e < e1; e++) {
        int s = g_csr[e];
        acc += fmaxf(g_bufC[(size_t)s * 256 + c] * sc + sh, 0.f) * (g_dis[s] * di);
    }
    g_h4lin[(size_t)i * 256 + c] = acc;
}

// ---------------- pooling with fused BN4 + relu (bufB 512-wide -> pooled) ----------------
__global__ void pool_bn_kernel(const float* __restrict__ gam, const float* __restrict__ bet) {
    int g = blockIdx.x;
    int c = blockIdx.y * 128 + threadIdx.x;   // 0..511
    float mean = g_sum[3 * 512 + c] * (1.f / NN);
    float var = g_sumsq[3 * 512 + c] * (1.f / NN) - mean * mean;
    float sc = gam[c] * rsqrtf(var + BN_EPS);
    float sh = bet[c] - mean * sc;
    int r0 = g_goff[g], r1 = g_goff[g + 1];
    float s = 0.f, mx = -1e30f;
    for (int r = r0; r < r1; r++) {
        float v = fmaxf(g_bufB[(size_t)r * 512 + c] * sc + sh, 0.f);
        s += v;
        mx = fmaxf(mx, v);
    }
    int cnt = r1 - r0;
    float meanp = s / (float)(cnt > 0 ? cnt : 1);
    if (cnt == 0) mx = 0.f;
    g_pooled[g * 1024 + c] = meanp;
    g_pooled[g * 1024 + 512 + c] = mx;
}

// ---------------- final FC: [32,1024] @ [1024,1024] ----------------
__global__ void fc_kernel(const float* __restrict__ w, const float* __restrict__ b,
                          float* __restrict__ out) {
    int mcol = blockIdx.x * 128 + threadIdx.x;
    int g0 = blockIdx.y * 8;
    float acc[8] = {0, 0, 0, 0, 0, 0, 0, 0};
    __shared__ float sp[8][64];
    for (int k0 = 0; k0 < 1024; k0 += 64) {
        for (int idx = threadIdx.x; idx < 512; idx += 128) {
            int gg = idx >> 6, kk = idx & 63;
            sp[gg][kk] = g_pooled[(g0 + gg) * 1024 + k0 + kk];
        }
        __syncthreads();
        for (int kk = 0; kk < 64; kk++) {
            float wv = w[(size_t)(k0 + kk) * 1024 + mcol];
            #pragma unroll
            for (int gg = 0; gg < 8; gg++) acc[gg] += sp[gg][kk] * wv;
        }
        __syncthreads();
    }
    float bb = b[mcol];
    #pragma unroll
    for (int gg = 0; gg < 8; gg++) out[(g0 + gg) * 1024 + mcol] = acc[gg] + bb;
}

// ---------------- host ----------------
extern "C" void kernel_launch(void* const* d_in, const int* in_sizes, int n_in,
                              void* d_out, int out_size) {
    const float* x        = (const float*)d_in[0];
    const int*   ei       = (const int*)d_in[1];
    const int*   batch    = (const int*)d_in[2];
    const float* gcn1_w   = (const float*)d_in[3];
    const float* gcn1_b   = (const float*)d_in[4];
    const float* sage_wl  = (const float*)d_in[5];
    const float* sage_wr  = (const float*)d_in[6];
    const float* sage_b   = (const float*)d_in[7];
    const float* gat_w    = (const float*)d_in[8];
    const float* gat_asrc = (const float*)d_in[9];
    const float* gat_adst = (const float*)d_in[10];
    const float* gat_b    = (const float*)d_in[11];
    const float* gcn4_w   = (const float*)d_in[12];
    const float* gcn4_b   = (const float*)d_in[13];
    const float* bn1_g    = (const float*)d_in[14];
    const float* bn1_b    = (const float*)d_in[15];
    const float* bn2_g    = (const float*)d_in[16];
    const float* bn2_b    = (const float*)d_in[17];
    const float* bn3_g    = (const float*)d_in[18];
    const float* bn3_b    = (const float*)d_in[19];
    const float* bn4_g    = (const float*)d_in[20];
    const float* bn4_b    = (const float*)d_in[21];
    const float* fc_w     = (const float*)d_in[22];
    const float* fc_b     = (const float*)d_in[23];
    const int* src = ei;
    const int* dst = ei + EE;
    float* out = (float*)d_out;

    // graph structure
    init_kernel<<<64, 256>>>();
    count_kernel<<<(EE + 255) / 256, 256>>>(dst, batch);
    scan_kernel<<<1, 1024>>>();
    fill_csr_kernel<<<(EE + 255) / 256, 256>>>(src, dst);

    // layer 1: GCN(5->64) + BN1 + ReLU (aggregate-then-linear)
    aggx_kernel<<<NN / 32, 256>>>(x);
    lin1_kernel<<<NN, 64>>>(gcn1_w, gcn1_b);                 // -> bufB (pre-BN1)
    bn_stats_kernel<<<256, 64>>>(1, 0);
    bn_apply_kernel<<<256, 64>>>(1, 3, 0, bn1_g, bn1_b);     // -> h1

    // layer 2: SAGE(64->128) + BN2 + ReLU (fused dual GEMM)
    sage_agg_kernel<<<NN, 64>>>();                           // -> bufA
    sgemm_kernel<<<dim3(1, NN / 128), 256>>>(0, sage_wl, 3, sage_wr,
                                             2 /*bufC*/, sage_b, 64, 64, 128);
    bn_stats_kernel<<<256, 128>>>(2, 1);
    bn_apply_kernel<<<256, 128>>>(2, 4, 1, bn2_g, bn2_b);    // -> h2

    // layer 3: GAT(128->1024, 4 heads of 256, head-mean); BN3 deferred
    sgemm_kernel<<<dim3(8, NN / 128), 256>>>(4, gat_w, -1, nullptr,
                                             6 /*hgat*/, nullptr, 128, 0, 1024);
    esed_kernel<<<NN, 1024>>>(gat_asrc, gat_adst);
    gat_agg_kernel<<<NN, 256>>>(gat_b);                      // -> bufC (pre-BN3)
    bn_stats_kernel<<<256, 256>>>(2, 2);

    // layer 4: GCN(256->512); BN3+relu fused into aggregation
    gcn_agg_bn_kernel<<<NN, 256>>>(bn3_g, bn3_b);            // bufC -> h4lin
    sgemm_kernel<<<dim3(4, NN / 128), 256>>>(5, gcn4_w, -1, nullptr,
                                             1 /*bufB*/, gcn4_b, 256, 0, 512);
    bn_stats_kernel<<<256, 512>>>(1, 3);

    // pooling (BN4+relu fused) + FC
    pool_bn_kernel<<<dim3(GG, 4), 128>>>(bn4_g, bn4_b);
    fc_kernel<<<dim3(8, 4), 128>>>(fc_w, fc_b, out);
}

// round 16
// speedup vs baseline: 1.5689x; 1.0862x over previous
#include <cuda_runtime.h>
#include <cstdint>

#define NN 16384
#define EE 131072
#define GG 32
#define BN_EPS 1e-5f

// ---------------- scratch (device globals; no allocation APIs) ----------------
__device__ float g_bufA[NN * 64];          // aggx (5-wide) / sage-agg (64-wide)
__device__ float g_bufB[NN * 512];         // lin1 out (64) / gcn4 gemm out (512)
__device__ float g_bufC[NN * 256];         // sage lin out (128) / gat out (256)
__device__ float g_h1[NN * 64];
__device__ float g_h2[NN * 128];
__device__ float g_h4lin[NN * 256];        // layer4 aggregated BN3(h) (256-wide)
__device__ float g_agg[NN * 512];          // GAT per-head alpha-weighted h2 (4x128)
__device__ float g_wstack[512 * 256];      // gat_w restacked [4*128, 256] * 0.25
__device__ float g_wsrc[512];              // W_h @ a_src[h]  (4 x 128)
__device__ float g_wdst[512];              // W_h @ a_dst[h]
__device__ float g_es[NN * 4];
__device__ float g_ed[NN * 4];
__device__ float g_dis[NN];
__device__ int   g_indeg[NN];
__device__ int   g_rowptr[NN + 1];
__device__ int   g_cursor[NN];
__device__ int   g_csr[EE];
__device__ int   g_gcnt[GG];
__device__ int   g_goff[GG + 1];
__device__ float g_sum[4 * 512];
__device__ float g_sumsq[4 * 512];
__device__ float g_pooled[GG * 1024];
__device__ float* g_bp[8];                 // buffer pointer table

__device__ __forceinline__ float lrelu(float x) { return x > 0.f ? x : 0.2f * x; }

// ---------------- setup: counts, sums, pointer table ----------------
__global__ void init_kernel() {
    int idx = blockIdx.x * blockDim.x + threadIdx.x;
    if (idx == 0) {
        g_bp[0] = g_bufA; g_bp[1] = g_bufB; g_bp[2] = g_bufC;
        g_bp[3] = g_h1;   g_bp[4] = g_h2;   g_bp[5] = g_h4lin;
        g_bp[6] = g_agg;  g_bp[7] = g_wstack;
    }
    if (idx < NN) g_indeg[idx] = 0;
    if (idx < GG) g_gcnt[idx] = 0;
    if (idx < 4 * 512) { g_sum[idx] = 0.f; g_sumsq[idx] = 0.f; }
    if (idx < 512) { g_wsrc[idx] = 0.f; g_wdst[idx] = 0.f; }
}

__global__ void count_kernel(const int* __restrict__ dst, const int* __restrict__ batch) {
    int idx = blockIdx.x * blockDim.x + threadIdx.x;
    if (idx < EE) atomicAdd(&g_indeg[dst[idx]], 1);
    if (idx < NN) atomicAdd(&g_gcnt[batch[idx]], 1);
}

// single-block exclusive scan of indeg -> rowptr/cursor; also dis and graph offsets
__global__ void scan_kernel() {
    __shared__ int partial[1024];
    int t = threadIdx.x;                 // blockDim = 1024, 16 elems/thread
    int base = t * 16;
    int local[16];
    int s = 0;
    #pragma unroll
    for (int j = 0; j < 16; j++) { local[j] = s; s += g_indeg[base + j]; }
    partial[t] = s;
    __syncthreads();
    for (int off = 1; off < 1024; off <<= 1) {
        int v = (t >= off) ? partial[t - off] : 0;
        __syncthreads();
        partial[t] += v;
        __syncthreads();
    }
    int pre = (t == 0) ? 0 : partial[t - 1];
    #pragma unroll
    for (int j = 0; j < 16; j++) {
        int v = pre + local[j];
        g_rowptr[base + j] = v;
        g_cursor[base + j] = v;
        g_dis[base + j] = rsqrtf((float)(g_indeg[base + j] + 1));
    }
    if (t == 1023) g_rowptr[NN] = partial[1023];
    if (t == 0) {
        int a = 0;
        for (int g = 0; g < GG; g++) { g_goff[g] = a; a += g_gcnt[g]; }
        g_goff[GG] = a;
    }
}

__global__ void fill_csr_kernel(const int* __restrict__ src, const int* __restrict__ dst) {
    int idx = blockIdx.x * blockDim.x + threadIdx.x;
    if (idx < EE) {
        int pos = atomicAdd(&g_cursor[dst[idx]], 1);
        g_csr[pos] = src[idx];
    }
}

// ---------------- layer 1: GCN aggregate on raw x (5-wide) ----------------
__global__ void aggx_kernel(const float* __restrict__ x) {
    int node = blockIdx.x * 32 + (threadIdx.x >> 3);
    int c = threadIdx.x & 7;
    if (c >= 5) return;
    float di = g_dis[node];
    float acc = x[node * 5 + c] * di * di;
    int e0 = g_rowptr[node], e1 = g_rowptr[node + 1];
    for (int e = e0; e < e1; e++) {
        int s = g_csr[e];
        acc += x[s * 5 + c] * (g_dis[s] * di);
    }
    g_bufA[node * 5 + c] = acc;
}

// ---------------- GCN1 linear (K=5 -> 64) with bias ----------------
__global__ void lin1_kernel(const float* __restrict__ w, const float* __restrict__ b) {
    int i = blockIdx.x, c = threadIdx.x;   // blockDim = 64
    float acc = b[c];
    #pragma unroll
    for (int k = 0; k < 5; k++) acc += g_bufA[i * 5 + k] * w[k * 64 + c];
    g_bufB[i * 64 + c] = acc;
}

// ---------------- SAGE mean aggregate (64-wide, h1 -> bufA) ----------------
__global__ void sage_agg_kernel() {
    int i = blockIdx.x, c = threadIdx.x;   // blockDim = 64
    int e0 = g_rowptr[i], e1 = g_rowptr[i + 1];
    float acc = 0.f;
    for (int e = e0; e < e1; e++) acc += g_h1[(size_t)g_csr[e] * 64 + c];
    int cnt = e1 - e0;
    g_bufA[i * 64 + c] = acc / (float)(cnt > 0 ? cnt : 1);
}

// ---------------- BN stats / apply (width = blockDim.x) ----------------
__global__ void bn_stats_kernel(int insel, int layer) {
    const float* __restrict__ h = g_bp[insel];
    int W = blockDim.x, c = threadIdx.x;
    float s = 0.f, s2 = 0.f;
    for (int r = blockIdx.x; r < NN; r += gridDim.x) {
        float v = h[(size_t)r * W + c];
        s += v; s2 += v * v;
    }
    atomicAdd(&g_sum[layer * 512 + c], s);
    atomicAdd(&g_sumsq[layer * 512 + c], s2);
}

__global__ void bn_apply_kernel(int insel, int outsel, int layer,
                                const float* __restrict__ gam, const float* __restrict__ bet) {
    const float* __restrict__ h = g_bp[insel];
    float* __restrict__ out = g_bp[outsel];
    int W = blockDim.x, c = threadIdx.x;
    float mean = g_sum[layer * 512 + c] * (1.f / NN);
    float var = g_sumsq[layer * 512 + c] * (1.f / NN) - mean * mean;
    float sc = gam[c] * rsqrtf(var + BN_EPS);
    float sh = bet[c] - mean * sc;
    for (int r = blockIdx.x; r < NN; r += gridDim.x) {
        float v = h[(size_t)r * W + c] * sc + sh;
        out[(size_t)r * W + c] = fmaxf(v, 0.f);
    }
}

// ---------------- SGEMM: C[NN,M] = A1[NN,K1]@B1 (+ A2[NN,K2]@B2) + bias ----------------
// Double-buffered smem, f32x2 packed FMA, conflict-free B reads.
// b1sel/b2sel >= 0 selects B from g_bp instead of the pointer args.
__global__ __launch_bounds__(256)
void sgemm_kernel(int a1sel, const float* B1p, int b1sel,
                  int a2sel, const float* B2p, int b2sel,
                  int csel, const float* __restrict__ bias,
                  int K1, int K2, int M) {
    const float* __restrict__ A1 = g_bp[a1sel];
    const float* __restrict__ A2 = (a2sel >= 0) ? g_bp[a2sel] : (const float*)0;
    const float* __restrict__ B1 = (b1sel >= 0) ? g_bp[b1sel] : B1p;
    const float* __restrict__ B2 = (b2sel >= 0) ? g_bp[b2sel] : B2p;
    float* __restrict__ C = g_bp[csel];
    __shared__ unsigned long long As2[2][8][128];   // A pre-duplicated (a,a) pairs
    __shared__ float Bs[2][8][128];

    int t = threadIdx.x;
    int r0 = blockIdx.y * 128, c0 = blockIdx.x * 128;
    int tx = t & 15, ty = t >> 4;
    int arow = t >> 1, acol = (t & 1) * 4;     // A: row arow, k-offset acol..acol+3
    int bk = t >> 5, bc = (t & 31) * 4;        // B: k-row bk, col bc..bc+3

    int T1 = K1 / 8;
    int T = T1 + ((a2sel >= 0) ? (K2 / 8) : 0);

    unsigned long long acc[8][4];
    #pragma unroll
    for (int i = 0; i < 8; i++)
        #pragma unroll
        for (int j = 0; j < 4; j++) acc[i][j] = 0ULL;

    float4 av, bv;
    {
        const float* Ap = A1 + (size_t)(r0 + arow) * K1 + acol;
        const float* Bp = B1 + (size_t)bk * M + c0 + bc;
        av = *(const float4*)Ap;
        bv = *(const float4*)Bp;
    }
    int buf = 0;
    {
        unsigned int a0 = __float_as_uint(av.x), a1 = __float_as_uint(av.y);
        unsigned int a2 = __float_as_uint(av.z), a3 = __float_as_uint(av.w);
        unsigned long long p;
        asm("mov.b64 %0, {%1,%1};" : "=l"(p) : "r"(a0)); As2[0][acol + 0][arow] = p;
        asm("mov.b64 %0, {%1,%1};" : "=l"(p) : "r"(a1)); As2[0][acol + 1][arow] = p;
        asm("mov.b64 %0, {%1,%1};" : "=l"(p) : "r"(a2)); As2[0][acol + 2][arow] = p;
        asm("mov.b64 %0, {%1,%1};" : "=l"(p) : "r"(a3)); As2[0][acol + 3][arow] = p;
        *(float4*)&Bs[0][bk][bc] = bv;
    }
    __syncthreads();

    for (int tt = 0; tt < T; tt++) {
        if (tt + 1 < T) {
            int nt = tt + 1;
            const float* Ap;
            const float* Bp;
            if (nt < T1) {
                Ap = A1 + (size_t)(r0 + arow) * K1 + nt * 8 + acol;
                Bp = B1 + (size_t)(nt * 8 + bk) * M + c0 + bc;
            } else {
                int mt = nt - T1;
                Ap = A2 + (size_t)(r0 + arow) * K2 + mt * 8 + acol;
                Bp = B2 + (size_t)(mt * 8 + bk) * M + c0 + bc;
            }
            av = *(const float4*)Ap;
            bv = *(const float4*)Bp;
        }

        #pragma unroll
        for (int k = 0; k < 8; k++) {
            const unsigned long long* brow = (const unsigned long long*)&Bs[buf][k][0];
            unsigned long long bp0 = brow[tx];
            unsigned long long bp1 = brow[tx + 16];
            unsigned long long bp2 = brow[tx + 32];
            unsigned long long bp3 = brow[tx + 48];
            #pragma unroll
            for (int i = 0; i < 8; i++) {
                unsigned long long ap = As2[buf][k][ty * 8 + i];
                asm("fma.rn.f32x2 %0, %1, %2, %0;" : "+l"(acc[i][0]) : "l"(ap), "l"(bp0));
                asm("fma.rn.f32x2 %0, %1, %2, %0;" : "+l"(acc[i][1]) : "l"(ap), "l"(bp1));
                asm("fma.rn.f32x2 %0, %1, %2, %0;" : "+l"(acc[i][2]) : "l"(ap), "l"(bp2));
                asm("fma.rn.f32x2 %0, %1, %2, %0;" : "+l"(acc[i][3]) : "l"(ap), "l"(bp3));
            }
        }

        if (tt + 1 < T) {
            int nb = buf ^ 1;
            unsigned int a0 = __float_as_uint(av.x), a1 = __float_as_uint(av.y);
            unsigned int a2 = __float_as_uint(av.z), a3 = __float_as_uint(av.w);
            unsigned long long p;
            asm("mov.b64 %0, {%1,%1};" : "=l"(p) : "r"(a0)); As2[nb][acol + 0][arow] = p;
            asm("mov.b64 %0, {%1,%1};" : "=l"(p) : "r"(a1)); As2[nb][acol + 1][arow] = p;
            asm("mov.b64 %0, {%1,%1};" : "=l"(p) : "r"(a2)); As2[nb][acol + 2][arow] = p;
            asm("mov.b64 %0, {%1,%1};" : "=l"(p) : "r"(a3)); As2[nb][acol + 3][arow] = p;
            *(float4*)&Bs[nb][bk][bc] = bv;
        }
        __syncthreads();
        buf ^= 1;
    }

    // epilogue: cols c0 + tx*2 + j*32
    float2 bb[4];
    if (bias) {
        const float2* bp2 = (const float2*)(bias + c0);
        #pragma unroll
        for (int j = 0; j < 4; j++) bb[j] = bp2[tx + j * 16];
    } else {
        #pragma unroll
        for (int j = 0; j < 4; j++) bb[j] = make_float2(0.f, 0.f);
    }
    #pragma unroll
    for (int i = 0; i < 8; i++) {
        int r = r0 + ty * 8 + i;
        float2* Cp = (float2*)(C + (size_t)r * M + c0) + tx;
        #pragma unroll
        for (int j = 0; j < 4; j++) {
            unsigned int lo, hi;
            asm("mov.b64 {%0,%1}, %2;" : "=r"(lo), "=r"(hi) : "l"(acc[i][j]));
            Cp[j * 16] = make_float2(__uint_as_float(lo) + bb[j].x,
                                     __uint_as_float(hi) + bb[j].y);
        }
    }
}

// ---------------- GAT: project attention vectors through W ----------------
// wsrc[h*128+k] = sum_c W[k, h*256+c] * asrc[h,c]   (atomic partial over c-chunks)
__global__ void wvec_kernel(const float* __restrict__ w,
                            const float* __restrict__ asrc, const float* __restrict__ adst) {
    int t = threadIdx.x;                   // 512: h = t>>7, k = t&127
    int h = t >> 7, k = t & 127;
    int c0 = blockIdx.x * 32;              // grid 8
    float s = 0.f, d = 0.f;
    for (int c = c0; c < c0 + 32; c++) {
        float wv = w[k * 1024 + h * 256 + c];
        s += wv * asrc[h * 256 + c];
        d += wv * adst[h * 256 + c];
    }
    atomicAdd(&g_wsrc[t], s);
    atomicAdd(&g_wdst[t], d);
}

// wstack[(h*128+k)*256 + c] = 0.25 * W[k, h*256+c]
__global__ void wstack_kernel(const float* __restrict__ w) {
    int idx = blockIdx.x * blockDim.x + threadIdx.x;   // 131072
    int kp = idx >> 8, c = idx & 255;
    int h = kp >> 7, k = kp & 127;
    g_wstack[idx] = 0.25f * w[k * 1024 + h * 256 + c];
}

// es[i,h] = h2[i] . wsrc[h];  ed[i,h] = h2[i] . wdst[h]
__global__ void esed2_kernel() {
    int idx = blockIdx.x * blockDim.x + threadIdx.x;   // NN*4
    int i = idx >> 2, h = idx & 3;
    const float* __restrict__ row = g_h2 + (size_t)i * 128;
    const float* __restrict__ ws = g_wsrc + h * 128;
    const float* __restrict__ wd = g_wdst + h * 128;
    float a = 0.f, b = 0.f;
    #pragma unroll 8
    for (int k = 0; k < 128; k++) {
        float v = row[k];
        a += v * ws[k];
        b += v * wd[k];
    }
    g_es[idx] = a;
    g_ed[idx] = b;
}

// ---------------- GAT aggregate: softmax-weighted h2 per head -> g_agg[NN,512] ----------------
__global__ void gat_agg2_kernel() {
    int i = blockIdx.x, t = threadIdx.x;   // blockDim = 128 (4 warps, warp = head)
    int e0 = g_rowptr[i];
    int deg = g_rowptr[i + 1] - e0;
    __shared__ float m[4], z[4];
    __shared__ float alpha[64 * 4];
    __shared__ int sid[64];
    int warp = t >> 5, lane = t & 31;

    {
        float edi = g_ed[i * 4 + warp];
        float mx = -1e30f;
        for (int j = lane; j <= deg; j += 32) {
            int s = (j < deg) ? g_csr[e0 + j] : i;
            mx = fmaxf(mx, lrelu(g_es[s * 4 + warp] + edi));
        }
        #pragma unroll
        for (int o = 16; o; o >>= 1) mx = fmaxf(mx, __shfl_xor_sync(0xffffffffu, mx, o));
        float zz = 0.f;
        for (int j = lane; j <= deg; j += 32) {
            int s = (j < deg) ? g_csr[e0 + j] : i;
            zz += __expf(lrelu(g_es[s * 4 + warp] + edi) - mx);
        }
        #pragma unroll
        for (int o = 16; o; o >>= 1) zz += __shfl_xor_sync(0xffffffffu, zz, o);
        if (lane == 0) { m[warp] = mx; z[warp] = zz; }
    }
    __syncthreads();

    float acc0 = 0.f, acc1 = 0.f, acc2 = 0.f, acc3 = 0.f;
    int k = t;   // feature 0..127
    for (int base = 0; base <= deg; base += 64) {
        int nj = deg + 1 - base; if (nj > 64) nj = 64;
        for (int u = t; u < nj * 4; u += 128) {
            int j = u >> 2, h = u & 3;
            int jj = base + j;
            int s = (jj < deg) ? g_csr[e0 + jj] : i;
            if (h == 0) sid[j] = s;
            float e = lrelu(g_es[s * 4 + h] + g_ed[i * 4 + h]);
            alpha[j * 4 + h] = __expf(e - m[h]) / z[h];
        }
        __syncthreads();
        for (int j = 0; j < nj; j++) {
            float v = g_h2[(size_t)sid[j] * 128 + k];
            acc0 += alpha[j * 4 + 0] * v;
            acc1 += alpha[j * 4 + 1] * v;
            acc2 += alpha[j * 4 + 2] * v;
            acc3 += alpha[j * 4 + 3] * v;
        }
        __syncthreads();
    }
    float* o = g_agg + (size_t)i * 512;
    o[k] = acc0;
    o[128 + k] = acc1;
    o[256 + k] = acc2;
    o[384 + k] = acc3;
}

// ---------------- layer 4 aggregate with fused BN3 + relu (bufC -> h4lin) ----------------
__global__ void gcn_agg_bn_kernel(const float* __restrict__ gam, const float* __restrict__ bet) {
    int i = blockIdx.x, c = threadIdx.x;   // blockDim = 256
    float mean = g_sum[2 * 512 + c] * (1.f / NN);
    float var = g_sumsq[2 * 512 + c] * (1.f / NN) - mean * mean;
    float sc = gam[c] * rsqrtf(var + BN_EPS);
    float sh = bet[c] - mean * sc;
    float di = g_dis[i];
    float acc = fmaxf(g_bufC[(size_t)i * 256 + c] * sc + sh, 0.f) * di * di;
    int e0 = g_rowptr[i], e1 = g_rowptr[i + 1];
    for (int e = e0; e < e1; e++) {
        int s = g_csr[e];
        acc += fmaxf(g_bufC[(size_t)s * 256 + c] * sc + sh, 0.f) * (g_dis[s] * di);
    }
    g_h4lin[(size_t)i * 256 + c] = acc;
}

// ---------------- pooling with fused BN4 + relu (bufB 512-wide -> pooled) ----------------
__global__ void pool_bn_kernel(const float* __restrict__ gam, const float* __restrict__ bet) {
    int g = blockIdx.x;
    int c = blockIdx.y * 128 + threadIdx.x;   // 0..511
    float mean = g_sum[3 * 512 + c] * (1.f / NN);
    float var = g_sumsq[3 * 512 + c] * (1.f / NN) - mean * mean;
    float sc = gam[c] * rsqrtf(var + BN_EPS);
    float sh = bet[c] - mean * sc;
    int r0 = g_goff[g], r1 = g_goff[g + 1];
    float s = 0.f, mx = -1e30f;
    for (int r = r0; r < r1; r++) {
        float v = fmaxf(g_bufB[(size_t)r * 512 + c] * sc + sh, 0.f);
        s += v;
        mx = fmaxf(mx, v);
    }
    int cnt = r1 - r0;
    float meanp = s / (float)(cnt > 0 ? cnt : 1);
    if (cnt == 0) mx = 0.f;
    g_pooled[g * 1024 + c] = meanp;
    g_pooled[g * 1024 + 512 + c] = mx;
}

// ---------------- final FC: [32,1024] @ [1024,1024] ----------------
__global__ void fc_kernel(const float* __restrict__ w, const float* __restrict__ b,
                          float* __restrict__ out) {
    int mcol = blockIdx.x * 128 + threadIdx.x;
    int g0 = blockIdx.y * 8;
    float acc[8] = {0, 0, 0, 0, 0, 0, 0, 0};
    __shared__ float sp[8][64];
    for (int k0 = 0; k0 < 1024; k0 += 64) {
        for (int idx = threadIdx.x; idx < 512; idx += 128) {
            int gg = idx >> 6, kk = idx & 63;
            sp[gg][kk] = g_pooled[(g0 + gg) * 1024 + k0 + kk];
        }
        __syncthreads();
        for (int kk = 0; kk < 64; kk++) {
            float wv = w[(size_t)(k0 + kk) * 1024 + mcol];
            #pragma unroll
            for (int gg = 0; gg < 8; gg++) acc[gg] += sp[gg][kk] * wv;
        }
        __syncthreads();
    }
    float bb = b[mcol];
    #pragma unroll
    for (int gg = 0; gg < 8; gg++) out[(g0 + gg) * 1024 + mcol] = acc[gg] + bb;
}

// ---------------- host ----------------
extern "C" void kernel_launch(void* const* d_in, const int* in_sizes, int n_in,
                              void* d_out, int out_size) {
    const float* x        = (const float*)d_in[0];
    const int*   ei       = (const int*)d_in[1];
    const int*   batch    = (const int*)d_in[2];
    const float* gcn1_w   = (const float*)d_in[3];
    const float* gcn1_b   = (const float*)d_in[4];
    const float* sage_wl  = (const float*)d_in[5];
    const float* sage_wr  = (const float*)d_in[6];
    const float* sage_b   = (const float*)d_in[7];
    const float* gat_w    = (const float*)d_in[8];
    const float* gat_asrc = (const float*)d_in[9];
    const float* gat_adst = (const float*)d_in[10];
    const float* gat_b    = (const float*)d_in[11];
    const float* gcn4_w   = (const float*)d_in[12];
    const float* gcn4_b   = (const float*)d_in[13];
    const float* bn1_g    = (const float*)d_in[14];
    const float* bn1_b    = (const float*)d_in[15];
    const float* bn2_g    = (const float*)d_in[16];
    const float* bn2_b    = (const float*)d_in[17];
    const float* bn3_g    = (const float*)d_in[18];
    const float* bn3_b    = (const float*)d_in[19];
    const float* bn4_g    = (const float*)d_in[20];
    const float* bn4_b    = (const float*)d_in[21];
    const float* fc_w     = (const float*)d_in[22];
    const float* fc_b     = (const float*)d_in[23];
    const int* src = ei;
    const int* dst = ei + EE;
    float* out = (float*)d_out;

    // graph structure + GAT weight preprocessing
    init_kernel<<<64, 256>>>();
    count_kernel<<<(EE + 255) / 256, 256>>>(dst, batch);
    scan_kernel<<<1, 1024>>>();
    fill_csr_kernel<<<(EE + 255) / 256, 256>>>(src, dst);
    wvec_kernel<<<8, 512>>>(gat_w, gat_asrc, gat_adst);
    wstack_kernel<<<512, 256>>>(gat_w);

    // layer 1: GCN(5->64) + BN1 + ReLU (aggregate-then-linear)
    aggx_kernel<<<NN / 32, 256>>>(x);
    lin1_kernel<<<NN, 64>>>(gcn1_w, gcn1_b);                 // -> bufB (pre-BN1)
    bn_stats_kernel<<<256, 64>>>(1, 0);
    bn_apply_kernel<<<256, 64>>>(1, 3, 0, bn1_g, bn1_b);     // -> h1

    // layer 2: SAGE(64->128) + BN2 + ReLU (fused dual GEMM)
    sage_agg_kernel<<<NN, 64>>>();                           // -> bufA
    sgemm_kernel<<<dim3(1, NN / 128), 256>>>(0, sage_wl, -1, 3, sage_wr, -1,
                                             2 /*bufC*/, sage_b, 64, 64, 128);
    bn_stats_kernel<<<256, 128>>>(2, 1);
    bn_apply_kernel<<<256, 128>>>(2, 4, 1, bn2_g, bn2_b);    // -> h2

    // layer 3: GAT — attention on h2 directly (GEMM commuted past softmax)
    esed2_kernel<<<NN * 4 / 256, 256>>>();
    gat_agg2_kernel<<<NN, 128>>>();                          // -> g_agg [NN,512]
    sgemm_kernel<<<dim3(2, NN / 128), 256>>>(6, nullptr, 7, -1, nullptr, -1,
                                             2 /*bufC*/, gat_b, 512, 0, 256);
    bn_stats_kernel<<<256, 256>>>(2, 2);

    // layer 4: GCN(256->512); BN3+relu fused into aggregation
    gcn_agg_bn_kernel<<<NN, 256>>>(bn3_g, bn3_b);            // bufC -> h4lin
    sgemm_kernel<<<dim3(4, NN / 128), 256>>>(5, gcn4_w, -1, -1, nullptr, -1,
                                             1 /*bufB*/, gcn4_b, 256, 0, 512);
    bn_stats_kernel<<<256, 512>>>(1, 3);

    // pooling (BN4+relu fused) + FC
    pool_bn_kernel<<<dim3(GG, 4), 128>>>(bn4_g, bn4_b);
    fc_kernel<<<dim3(8, 4), 128>>>(fc_w, fc_b, out);
}

// round 17
// speedup vs baseline: 1.7611x; 1.1225x over previous
#include <cuda_runtime.h>
#include <cstdint>

#define NN 16384
#define EE 131072
#define GG 32
#define BN_EPS 1e-5f

// ---------------- scratch (device globals; no allocation APIs) ----------------
__device__ float g_bufA[NN * 64];          // aggx (5-wide) / sage-agg (64-wide)
__device__ float g_bufB[NN * 512];         // gcn4 gemm out (512)
__device__ float g_bufC[NN * 256];         // sage lin out (128) / gat out (256)
__device__ float g_h1[NN * 64];
__device__ float g_h2[NN * 128];
__device__ float g_h4lin[NN * 256];        // layer4 aggregated BN3(h) (256-wide)
__device__ float g_agg[NN * 512];          // GAT per-head alpha-weighted h2 (4x128)
__device__ float g_wstack[512 * 256];      // gat_w restacked [4*128, 256] * 0.25
__device__ float g_wsrc[512];              // W_h @ a_src[h]  (4 x 128)
__device__ float g_wdst[512];              // W_h @ a_dst[h]
__device__ float g_es[NN * 4];
__device__ float g_ed[NN * 4];
__device__ float g_dis[NN];
__device__ int   g_indeg[NN];
__device__ int   g_rowptr[NN + 1];
__device__ int   g_cursor[NN];
__device__ int   g_csr[EE];
__device__ int   g_gcnt[GG];
__device__ int   g_goff[GG + 1];
__device__ float g_sum[4 * 512];
__device__ float g_sumsq[4 * 512];
__device__ float g_cov[30];                // layer-1 analytic stats: 5 means + 25 second moments
__device__ float g_pooled[GG * 1024];
__device__ float* g_bp[8];                 // buffer pointer table

__device__ __forceinline__ float lrelu(float x) { return x > 0.f ? x : 0.2f * x; }

// ---------------- setup: counts, sums, pointer table ----------------
__global__ void init_kernel() {
    int idx = blockIdx.x * blockDim.x + threadIdx.x;
    if (idx == 0) {
        g_bp[0] = g_bufA; g_bp[1] = g_bufB; g_bp[2] = g_bufC;
        g_bp[3] = g_h1;   g_bp[4] = g_h2;   g_bp[5] = g_h4lin;
        g_bp[6] = g_agg;  g_bp[7] = g_wstack;
    }
    if (idx < NN) g_indeg[idx] = 0;
    if (idx < GG) g_gcnt[idx] = 0;
    if (idx < 4 * 512) { g_sum[idx] = 0.f; g_sumsq[idx] = 0.f; }
    if (idx < 512) { g_wsrc[idx] = 0.f; g_wdst[idx] = 0.f; }
    if (idx < 30) g_cov[idx] = 0.f;
}

__global__ void count_kernel(const int* __restrict__ dst, const int* __restrict__ batch) {
    int idx = blockIdx.x * blockDim.x + threadIdx.x;
    if (idx < EE) atomicAdd(&g_indeg[dst[idx]], 1);
    if (idx < NN) atomicAdd(&g_gcnt[batch[idx]], 1);
}

// single-block exclusive scan of indeg -> rowptr/cursor; also dis and graph offsets
__global__ void scan_kernel() {
    __shared__ int partial[1024];
    int t = threadIdx.x;                 // blockDim = 1024, 16 elems/thread
    int base = t * 16;
    int local[16];
    int s = 0;
    #pragma unroll
    for (int j = 0; j < 16; j++) { local[j] = s; s += g_indeg[base + j]; }
    partial[t] = s;
    __syncthreads();
    for (int off = 1; off < 1024; off <<= 1) {
        int v = (t >= off) ? partial[t - off] : 0;
        __syncthreads();
        partial[t] += v;
        __syncthreads();
    }
    int pre = (t == 0) ? 0 : partial[t - 1];
    #pragma unroll
    for (int j = 0; j < 16; j++) {
        int v = pre + local[j];
        g_rowptr[base + j] = v;
        g_cursor[base + j] = v;
        g_dis[base + j] = rsqrtf((float)(g_indeg[base + j] + 1));
    }
    if (t == 1023) g_rowptr[NN] = partial[1023];
    if (t == 0) {
        int a = 0;
        for (int g = 0; g < GG; g++) { g_goff[g] = a; a += g_gcnt[g]; }
        g_goff[GG] = a;
    }
}

__global__ void fill_csr_kernel(const int* __restrict__ src, const int* __restrict__ dst) {
    int idx = blockIdx.x * blockDim.x + threadIdx.x;
    if (idx < EE) {
        int pos = atomicAdd(&g_cursor[dst[idx]], 1);
        g_csr[pos] = src[idx];
    }
}

// ---------------- layer 1: GCN aggregate on raw x (5-wide) ----------------
__global__ void aggx_kernel(const float* __restrict__ x) {
    int node = blockIdx.x * 32 + (threadIdx.x >> 3);
    int c = threadIdx.x & 7;
    if (c >= 5) return;
    float di = g_dis[node];
    float acc = x[node * 5 + c] * di * di;
    int e0 = g_rowptr[node], e1 = g_rowptr[node + 1];
    for (int e = e0; e < e1; e++) {
        int s = g_csr[e];
        acc += x[s * 5 + c] * (g_dis[s] * di);
    }
    g_bufA[node * 5 + c] = acc;
}

// ---------------- layer-1 analytic BN stats: mean + second moments of aggx ----------------
__global__ void cov5_kernel() {      // grid 64, block 256: one row per thread
    int idx = blockIdx.x * 256 + threadIdx.x;
    int lane = threadIdx.x & 31;
    float a[5];
    #pragma unroll
    for (int k = 0; k < 5; k++) a[k] = g_bufA[idx * 5 + k];
    float vals[30];
    #pragma unroll
    for (int k = 0; k < 5; k++) vals[k] = a[k];
    #pragma unroll
    for (int k = 0; k < 5; k++)
        #pragma unroll
        for (int l = 0; l < 5; l++) vals[5 + k * 5 + l] = a[k] * a[l];
    __shared__ float acc[30];
    if (threadIdx.x < 30) acc[threadIdx.x] = 0.f;
    __syncthreads();
    #pragma unroll
    for (int v = 0; v < 30; v++) {
        float s = vals[v];
        #pragma unroll
        for (int o = 16; o; o >>= 1) s += __shfl_xor_sync(0xffffffffu, s, o);
        if (lane == 0) atomicAdd(&acc[v], s);
    }
    __syncthreads();
    if (threadIdx.x < 30) atomicAdd(&g_cov[threadIdx.x], acc[threadIdx.x]);
}

// Solve layer-0 BN stats analytically: y = w.a + b  ->  E[y], E[y^2]
__global__ void solve1_kernel(const float* __restrict__ w, const float* __restrict__ b) {
    int c = threadIdx.x;                 // 64
    float m[5], S[25];
    #pragma unroll
    for (int k = 0; k < 5; k++) m[k] = g_cov[k] * (1.f / NN);
    #pragma unroll
    for (int u = 0; u < 25; u++) S[u] = g_cov[5 + u] * (1.f / NN);
    float wc[5];
    #pragma unroll
    for (int k = 0; k < 5; k++) wc[k] = w[k * 64 + c];
    float bc = b[c];
    float wm = 0.f;
    #pragma unroll
    for (int k = 0; k < 5; k++) wm += wc[k] * m[k];
    float wSw = 0.f;
    #pragma unroll
    for (int k = 0; k < 5; k++)
        #pragma unroll
        for (int l = 0; l < 5; l++) wSw += wc[k] * wc[l] * S[k * 5 + l];
    float Ey = wm + bc;
    float Ey2 = wSw + 2.f * bc * wm + bc * bc;
    g_sum[c] = Ey * NN;
    g_sumsq[c] = Ey2 * NN;
}

// ---------------- GCN1 linear (K=5 -> 64) with fused BN1 + ReLU ----------------
__global__ void lin1bn_kernel(const float* __restrict__ w, const float* __restrict__ b,
                              const float* __restrict__ gam, const float* __restrict__ bet) {
    int i = blockIdx.x, c = threadIdx.x;   // blockDim = 64
    float mean = g_sum[c] * (1.f / NN);
    float var = g_sumsq[c] * (1.f / NN) - mean * mean;
    float sc = gam[c] * rsqrtf(var + BN_EPS);
    float sh = bet[c] - mean * sc;
    float acc = b[c];
    #pragma unroll
    for (int k = 0; k < 5; k++) acc += g_bufA[i * 5 + k] * w[k * 64 + c];
    g_h1[i * 64 + c] = fmaxf(acc * sc + sh, 0.f);
}

// ---------------- SAGE mean aggregate (64-wide, h1 -> bufA) ----------------
__global__ void sage_agg_kernel() {
    int i = blockIdx.x, c = threadIdx.x;   // blockDim = 64
    int e0 = g_rowptr[i], e1 = g_rowptr[i + 1];
    float acc = 0.f;
    for (int e = e0; e < e1; e++) acc += g_h1[(size_t)g_csr[e] * 64 + c];
    int cnt = e1 - e0;
    g_bufA[i * 64 + c] = acc / (float)(cnt > 0 ? cnt : 1);
}

// ---------------- SGEMM: C[NN,M] = A1@B1 (+ A2@B2) + bias, optional fused BN stats --------
// Double-buffered smem, f32x2 packed FMA, conflict-free B reads.
// b1sel/b2sel >= 0 selects B from g_bp instead of the pointer args.
// stats_layer >= 0: accumulate per-column sum/sumsq of C into g_sum/g_sumsq[layer].
__global__ __launch_bounds__(256)
void sgemm_kernel(int a1sel, const float* B1p, int b1sel,
                  int a2sel, const float* B2p, int b2sel,
                  int csel, const float* __restrict__ bias,
                  int K1, int K2, int M, int stats_layer) {
    const float* __restrict__ A1 = g_bp[a1sel];
    const float* __restrict__ A2 = (a2sel >= 0) ? g_bp[a2sel] : (const float*)0;
    const float* __restrict__ B1 = (b1sel >= 0) ? g_bp[b1sel] : B1p;
    const float* __restrict__ B2 = (b2sel >= 0) ? g_bp[b2sel] : B2p;
    float* __restrict__ C = g_bp[csel];
    __shared__ unsigned long long As2[2][8][128];   // A pre-duplicated (a,a) pairs
    __shared__ float Bs[2][8][128];
    __shared__ float s_s[128], s_q[128];

    int t = threadIdx.x;
    int r0 = blockIdx.y * 128, c0 = blockIdx.x * 128;
    int tx = t & 15, ty = t >> 4;
    int arow = t >> 1, acol = (t & 1) * 4;     // A: row arow, k-offset acol..acol+3
    int bk = t >> 5, bc = (t & 31) * 4;        // B: k-row bk, col bc..bc+3

    int T1 = K1 / 8;
    int T = T1 + ((a2sel >= 0) ? (K2 / 8) : 0);

    unsigned long long acc[8][4];
    #pragma unroll
    for (int i = 0; i < 8; i++)
        #pragma unroll
        for (int j = 0; j < 4; j++) acc[i][j] = 0ULL;

    float4 av, bv;
    {
        const float* Ap = A1 + (size_t)(r0 + arow) * K1 + acol;
        const float* Bp = B1 + (size_t)bk * M + c0 + bc;
        av = *(const float4*)Ap;
        bv = *(const float4*)Bp;
    }
    int buf = 0;
    {
        unsigned int a0 = __float_as_uint(av.x), a1 = __float_as_uint(av.y);
        unsigned int a2 = __float_as_uint(av.z), a3 = __float_as_uint(av.w);
        unsigned long long p;
        asm("mov.b64 %0, {%1,%1};" : "=l"(p) : "r"(a0)); As2[0][acol + 0][arow] = p;
        asm("mov.b64 %0, {%1,%1};" : "=l"(p) : "r"(a1)); As2[0][acol + 1][arow] = p;
        asm("mov.b64 %0, {%1,%1};" : "=l"(p) : "r"(a2)); As2[0][acol + 2][arow] = p;
        asm("mov.b64 %0, {%1,%1};" : "=l"(p) : "r"(a3)); As2[0][acol + 3][arow] = p;
        *(float4*)&Bs[0][bk][bc] = bv;
    }
    if (stats_layer >= 0 && t < 128) { s_s[t] = 0.f; s_q[t] = 0.f; }
    __syncthreads();

    for (int tt = 0; tt < T; tt++) {
        if (tt + 1 < T) {
            int nt = tt + 1;
            const float* Ap;
            const float* Bp;
            if (nt < T1) {
                Ap = A1 + (size_t)(r0 + arow) * K1 + nt * 8 + acol;
                Bp = B1 + (size_t)(nt * 8 + bk) * M + c0 + bc;
            } else {
                int mt = nt - T1;
                Ap = A2 + (size_t)(r0 + arow) * K2 + mt * 8 + acol;
                Bp = B2 + (size_t)(mt * 8 + bk) * M + c0 + bc;
            }
            av = *(const float4*)Ap;
            bv = *(const float4*)Bp;
        }

        #pragma unroll
        for (int k = 0; k < 8; k++) {
            const unsigned long long* brow = (const unsigned long long*)&Bs[buf][k][0];
            unsigned long long bp0 = brow[tx];
            unsigned long long bp1 = brow[tx + 16];
            unsigned long long bp2 = brow[tx + 32];
            unsigned long long bp3 = brow[tx + 48];
            #pragma unroll
            for (int i = 0; i < 8; i++) {
                unsigned long long ap = As2[buf][k][ty * 8 + i];
                asm("fma.rn.f32x2 %0, %1, %2, %0;" : "+l"(acc[i][0]) : "l"(ap), "l"(bp0));
                asm("fma.rn.f32x2 %0, %1, %2, %0;" : "+l"(acc[i][1]) : "l"(ap), "l"(bp1));
                asm("fma.rn.f32x2 %0, %1, %2, %0;" : "+l"(acc[i][2]) : "l"(ap), "l"(bp2));
                asm("fma.rn.f32x2 %0, %1, %2, %0;" : "+l"(acc[i][3]) : "l"(ap), "l"(bp3));
            }
        }

        if (tt + 1 < T) {
            int nb = buf ^ 1;
            unsigned int a0 = __float_as_uint(av.x), a1 = __float_as_uint(av.y);
            unsigned int a2 = __float_as_uint(av.z), a3 = __float_as_uint(av.w);
            unsigned long long p;
            asm("mov.b64 %0, {%1,%1};" : "=l"(p) : "r"(a0)); As2[nb][acol + 0][arow] = p;
            asm("mov.b64 %0, {%1,%1};" : "=l"(p) : "r"(a1)); As2[nb][acol + 1][arow] = p;
            asm("mov.b64 %0, {%1,%1};" : "=l"(p) : "r"(a2)); As2[nb][acol + 2][arow] = p;
            asm("mov.b64 %0, {%1,%1};" : "=l"(p) : "r"(a3)); As2[nb][acol + 3][arow] = p;
            *(float4*)&Bs[nb][bk][bc] = bv;
        }
        __syncthreads();
        buf ^= 1;
    }

    // epilogue: cols c0 + tx*2 + j*32 (+half)
    float2 bb[4];
    if (bias) {
        const float2* bp2 = (const float2*)(bias + c0);
        #pragma unroll
        for (int j = 0; j < 4; j++) bb[j] = bp2[tx + j * 16];
    } else {
        #pragma unroll
        for (int j = 0; j < 4; j++) bb[j] = make_float2(0.f, 0.f);
    }
    float ps[4][2] = {{0,0},{0,0},{0,0},{0,0}};
    float pq[4][2] = {{0,0},{0,0},{0,0},{0,0}};
    #pragma unroll
    for (int i = 0; i < 8; i++) {
        int r = r0 + ty * 8 + i;
        float2* Cp = (float2*)(C + (size_t)r * M + c0) + tx;
        #pragma unroll
        for (int j = 0; j < 4; j++) {
            unsigned int lo, hi;
            asm("mov.b64 {%0,%1}, %2;" : "=r"(lo), "=r"(hi) : "l"(acc[i][j]));
            float v0 = __uint_as_float(lo) + bb[j].x;
            float v1 = __uint_as_float(hi) + bb[j].y;
            Cp[j * 16] = make_float2(v0, v1);
            ps[j][0] += v0; pq[j][0] += v0 * v0;
            ps[j][1] += v1; pq[j][1] += v1 * v1;
        }
    }
    if (stats_layer >= 0) {
        #pragma unroll
        for (int j = 0; j < 4; j++) {
            int cl = tx * 2 + j * 32;
            atomicAdd(&s_s[cl], ps[j][0]);     atomicAdd(&s_q[cl], pq[j][0]);
            atomicAdd(&s_s[cl + 1], ps[j][1]); atomicAdd(&s_q[cl + 1], pq[j][1]);
        }
        __syncthreads();
        if (t < 128) {
            atomicAdd(&g_sum[stats_layer * 512 + c0 + t], s_s[t]);
            atomicAdd(&g_sumsq[stats_layer * 512 + c0 + t], s_q[t]);
        }
    }
}

// ---------------- GAT: project attention vectors through W ----------------
__global__ void wvec_kernel(const float* __restrict__ w,
                            const float* __restrict__ asrc, const float* __restrict__ adst) {
    int t = threadIdx.x;                   // 512: h = t>>7, k = t&127
    int h = t >> 7, k = t & 127;
    int c0 = blockIdx.x * 32;              // grid 8
    float s = 0.f, d = 0.f;
    for (int c = c0; c < c0 + 32; c++) {
        float wv = w[k * 1024 + h * 256 + c];
        s += wv * asrc[h * 256 + c];
        d += wv * adst[h * 256 + c];
    }
    atomicAdd(&g_wsrc[t], s);
    atomicAdd(&g_wdst[t], d);
}

// wstack[(h*128+k)*256 + c] = 0.25 * W[k, h*256+c]
__global__ void wstack_kernel(const float* __restrict__ w) {
    int idx = blockIdx.x * blockDim.x + threadIdx.x;   // 131072
    int kp = idx >> 8, c = idx & 255;
    int h = kp >> 7, k = kp & 127;
    g_wstack[idx] = 0.25f * w[k * 1024 + h * 256 + c];
}

// ---------------- BN2 apply + es/ed projection, fused (bufC -> h2, es, ed) ----------------
// grid 2048 x 256 (8 warps); warp w handles row i = blockIdx*8 + w.
__global__ void bn_apply_esed_kernel(const float* __restrict__ gam, const float* __restrict__ bet) {
    __shared__ float sws[512], swd[512], ssc[128], ssh[128];
    int t = threadIdx.x;
    for (int u = t; u < 512; u += 256) { sws[u] = g_wsrc[u]; swd[u] = g_wdst[u]; }
    if (t < 128) {
        float mean = g_sum[512 + t] * (1.f / NN);
        float var = g_sumsq[512 + t] * (1.f / NN) - mean * mean;
        float sc = gam[t] * rsqrtf(var + BN_EPS);
        ssc[t] = sc;
        ssh[t] = bet[t] - mean * sc;
    }
    __syncthreads();
    int warp = t >> 5, lane = t & 31;
    int i = blockIdx.x * 8 + warp;
    const float* __restrict__ row = g_bufC + (size_t)i * 128;
    float* __restrict__ orow = g_h2 + (size_t)i * 128;
    float es_[4] = {0.f, 0.f, 0.f, 0.f}, ed_[4] = {0.f, 0.f, 0.f, 0.f};
    #pragma unroll
    for (int q = 0; q < 4; q++) {
        int c = q * 32 + lane;
        float vv = fmaxf(row[c] * ssc[c] + ssh[c], 0.f);
        orow[c] = vv;
        #pragma unroll
        for (int h = 0; h < 4; h++) {
            es_[h] += vv * sws[h * 128 + c];
            ed_[h] += vv * swd[h * 128 + c];
        }
    }
    #pragma unroll
    for (int h = 0; h < 4; h++) {
        #pragma unroll
        for (int o = 16; o; o >>= 1) {
            es_[h] += __shfl_xor_sync(0xffffffffu, es_[h], o);
            ed_[h] += __shfl_xor_sync(0xffffffffu, ed_[h], o);
        }
    }
    if (lane == 0) {
        #pragma unroll
        for (int h = 0; h < 4; h++) {
            g_es[i * 4 + h] = es_[h];
            g_ed[i * 4 + h] = ed_[h];
        }
    }
}

// ---------------- GAT aggregate: softmax-weighted h2 per head -> g_agg[NN,512] ----------------
__global__ void gat_agg2_kernel() {
    int i = blockIdx.x, t = threadIdx.x;   // blockDim = 128 (4 warps, warp = head)
    int e0 = g_rowptr[i];
    int deg = g_rowptr[i + 1] - e0;
    __shared__ float m[4], z[4];
    __shared__ float alpha[64 * 4];
    __shared__ int sid[64];
    int warp = t >> 5, lane = t & 31;

    {
        float edi = g_ed[i * 4 + warp];
        float mx = -1e30f;
        for (int j = lane; j <= deg; j += 32) {
            int s = (j < deg) ? g_csr[e0 + j] : i;
            mx = fmaxf(mx, lrelu(g_es[s * 4 + warp] + edi));
        }
        #pragma unroll
        for (int o = 16; o; o >>= 1) mx = fmaxf(mx, __shfl_xor_sync(0xffffffffu, mx, o));
        float zz = 0.f;
        for (int j = lane; j <= deg; j += 32) {
            int s = (j < deg) ? g_csr[e0 + j] : i;
            zz += __expf(lrelu(g_es[s * 4 + warp] + edi) - mx);
        }
        #pragma unroll
        for (int o = 16; o; o >>= 1) zz += __shfl_xor_sync(0xffffffffu, zz, o);
        if (lane == 0) { m[warp] = mx; z[warp] = zz; }
    }
    __syncthreads();

    float acc0 = 0.f, acc1 = 0.f, acc2 = 0.f, acc3 = 0.f;
    int k = t;   // feature 0..127
    for (int base = 0; base <= deg; base += 64) {
        int nj = deg + 1 - base; if (nj > 64) nj = 64;
        for (int u = t; u < nj * 4; u += 128) {
            int j = u >> 2, h = u & 3;
            int jj = base + j;
            int s = (jj < deg) ? g_csr[e0 + jj] : i;
            if (h == 0) sid[j] = s;
            float e = lrelu(g_es[s * 4 + h] + g_ed[i * 4 + h]);
            alpha[j * 4 + h] = __expf(e - m[h]) / z[h];
        }
        __syncthreads();
        for (int j = 0; j < nj; j++) {
            float v = g_h2[(size_t)sid[j] * 128 + k];
            acc0 += alpha[j * 4 + 0] * v;
            acc1 += alpha[j * 4 + 1] * v;
            acc2 += alpha[j * 4 + 2] * v;
            acc3 += alpha[j * 4 + 3] * v;
        }
        __syncthreads();
    }
    float* o = g_agg + (size_t)i * 512;
    o[k] = acc0;
    o[128 + k] = acc1;
    o[256 + k] = acc2;
    o[384 + k] = acc3;
}

// ---------------- layer 4 aggregate with fused BN3 + relu (bufC -> h4lin) ----------------
__global__ void gcn_agg_bn_kernel(const float* __restrict__ gam, const float* __restrict__ bet) {
    int i = blockIdx.x, c = threadIdx.x;   // blockDim = 256
    float mean = g_sum[2 * 512 + c] * (1.f / NN);
    float var = g_sumsq[2 * 512 + c] * (1.f / NN) - mean * mean;
    float sc = gam[c] * rsqrtf(var + BN_EPS);
    float sh = bet[c] - mean * sc;
    float di = g_dis[i];
    float acc = fmaxf(g_bufC[(size_t)i * 256 + c] * sc + sh, 0.f) * di * di;
    int e0 = g_rowptr[i], e1 = g_rowptr[i + 1];
    for (int e = e0; e < e1; e++) {
        int s = g_csr[e];
        acc += fmaxf(g_bufC[(size_t)s * 256 + c] * sc + sh, 0.f) * (g_dis[s] * di);
    }
    g_h4lin[(size_t)i * 256 + c] = acc;
}

// ---------------- pooling with fused BN4 + relu (bufB 512-wide -> pooled) ----------------
__global__ void pool_bn_kernel(const float* __restrict__ gam, const float* __restrict__ bet) {
    int g = blockIdx.x;
    int c = blockIdx.y * 128 + threadIdx.x;   // 0..511
    float mean = g_sum[3 * 512 + c] * (1.f / NN);
    float var = g_sumsq[3 * 512 + c] * (1.f / NN) - mean * mean;
    float sc = gam[c] * rsqrtf(var + BN_EPS);
    float sh = bet[c] - mean * sc;
    int r0 = g_goff[g], r1 = g_goff[g + 1];
    float s = 0.f, mx = -1e30f;
    for (int r = r0; r < r1; r++) {
        float v = fmaxf(g_bufB[(size_t)r * 512 + c] * sc + sh, 0.f);
        s += v;
        mx = fmaxf(mx, v);
    }
    int cnt = r1 - r0;
    float meanp = s / (float)(cnt > 0 ? cnt : 1);
    if (cnt == 0) mx = 0.f;
    g_pooled[g * 1024 + c] = meanp;
    g_pooled[g * 1024 + 512 + c] = mx;
}

// ---------------- final FC: [32,1024] @ [1024,1024] ----------------
__global__ void fc_kernel(const float* __restrict__ w, const float* __restrict__ b,
                          float* __restrict__ out) {
    int mcol = blockIdx.x * 128 + threadIdx.x;
    int g0 = blockIdx.y * 8;
    float acc[8] = {0, 0, 0, 0, 0, 0, 0, 0};
    __shared__ float sp[8][64];
    for (int k0 = 0; k0 < 1024; k0 += 64) {
        for (int idx = threadIdx.x; idx < 512; idx += 128) {
            int gg = idx >> 6, kk = idx & 63;
            sp[gg][kk] = g_pooled[(g0 + gg) * 1024 + k0 + kk];
        }
        __syncthreads();
        for (int kk = 0; kk < 64; kk++) {
            float wv = w[(size_t)(k0 + kk) * 1024 + mcol];
            #pragma unroll
            for (int gg = 0; gg < 8; gg++) acc[gg] += sp[gg][kk] * wv;
        }
        __syncthreads();
    }
    float bb = b[mcol];
    #pragma unroll
    for (int gg = 0; gg < 8; gg++) out[(g0 + gg) * 1024 + mcol] = acc[gg] + bb;
}

// ---------------- host ----------------
extern "C" void kernel_launch(void* const* d_in, const int* in_sizes, int n_in,
                              void* d_out, int out_size) {
    const float* x        = (const float*)d_in[0];
    const int*   ei       = (const int*)d_in[1];
    const int*   batch    = (const int*)d_in[2];
    const float* gcn1_w   = (const float*)d_in[3];
    const float* gcn1_b   = (const float*)d_in[4];
    const float* sage_wl  = (const float*)d_in[5];
    const float* sage_wr  = (const float*)d_in[6];
    const float* sage_b   = (const float*)d_in[7];
    const float* gat_w    = (const float*)d_in[8];
    const float* gat_asrc = (const float*)d_in[9];
    const float* gat_adst = (const float*)d_in[10];
    const float* gat_b    = (const float*)d_in[11];
    const float* gcn4_w   = (const float*)d_in[12];
    const float* gcn4_b   = (const float*)d_in[13];
    const float* bn1_g    = (const float*)d_in[14];
    const float* bn1_b    = (const float*)d_in[15];
    const float* bn2_g    = (const float*)d_in[16];
    const float* bn2_b    = (const float*)d_in[17];
    const float* bn3_g    = (const float*)d_in[18];
    const float* bn3_b    = (const float*)d_in[19];
    const float* bn4_g    = (const float*)d_in[20];
    const float* bn4_b    = (const float*)d_in[21];
    const float* fc_w     = (const float*)d_in[22];
    const float* fc_b     = (const float*)d_in[23];
    const int* src = ei;
    const int* dst = ei + EE;
    float* out = (float*)d_out;

    // graph structure + GAT weight preprocessing
    init_kernel<<<64, 256>>>();
    count_kernel<<<(EE + 255) / 256, 256>>>(dst, batch);
    scan_kernel<<<1, 1024>>>();
    fill_csr_kernel<<<(EE + 255) / 256, 256>>>(src, dst);
    wvec_kernel<<<8, 512>>>(gat_w, gat_asrc, gat_adst);
    wstack_kernel<<<512, 256>>>(gat_w);

    // layer 1: GCN(5->64) + BN1 + ReLU (aggregate, analytic stats, fused linear+BN)
    aggx_kernel<<<NN / 32, 256>>>(x);
    cov5_kernel<<<64, 256>>>();
    solve1_kernel<<<1, 64>>>(gcn1_w, gcn1_b);
    lin1bn_kernel<<<NN, 64>>>(gcn1_w, gcn1_b, bn1_g, bn1_b);   // -> h1

    // layer 2: SAGE(64->128), stats fused in GEMM epilogue
    sage_agg_kernel<<<NN, 64>>>();                             // -> bufA
    sgemm_kernel<<<dim3(1, NN / 128), 256>>>(0, sage_wl, -1, 3, sage_wr, -1,
                                             2 /*bufC*/, sage_b, 64, 64, 128, 1);
    bn_apply_esed_kernel<<<NN / 8, 256>>>(bn2_g, bn2_b);       // -> h2, es, ed

    // layer 3: GAT — attention on h2, GEMM commuted past softmax; stats fused
    gat_agg2_kernel<<<NN, 128>>>();                            // -> g_agg [NN,512]
    sgemm_kernel<<<dim3(2, NN / 128), 256>>>(6, nullptr, 7, -1, nullptr, -1,
                                             2 /*bufC*/, gat_b, 512, 0, 256, 2);

    // layer 4: GCN(256->512); BN3+relu fused into aggregation; stats fused in GEMM
    gcn_agg_bn_kernel<<<NN, 256>>>(bn3_g, bn3_b);              // bufC -> h4lin
    sgemm_kernel<<<dim3(4, NN / 128), 256>>>(5, gcn4_w, -1, -1, nullptr, -1,
                                             1 /*bufB*/, gcn4_b, 256, 0, 512, 3);

    // pooling (BN4+relu fused) + FC
    pool_bn_kernel<<<dim3(GG, 4), 128>>>(bn4_g, bn4_b);
    fc_kernel<<<dim3(8, 4), 128>>>(fc_w, fc_b, out);
}